// round 7
// baseline (speedup 1.0000x reference)
#include <cuda_runtime.h>
#include <cuda_bf16.h>
#include <math.h>
#include <stdint.h>

#define Bb   8
#define Cc   256
#define Nn   2304
#define Mtot (Bb*Nn)
#define EPSf 1e-5f

// ---------------------------------------------------------------------------
// Scratch
// ---------------------------------------------------------------------------
__device__ __align__(128) __nv_bfloat16 g_q[2][(size_t)Mtot*Cc];
__device__ __align__(128) __nv_bfloat16 g_k[2][(size_t)Mtot*Cc];
__device__ __align__(128) __nv_bfloat16 g_v[2][(size_t)Mtot*Cc];
__device__ __align__(128) __nv_bfloat16 g_attn [(size_t)Bb*Nn*Nn];   // bf16 logits
__device__ __align__(128) __nv_bfloat16 g_attnb[(size_t)Bb*Nn*Nn];   // bf16 probs
__device__ __align__(128) __nv_bfloat16 g_outT[2][(size_t)Bb*Cc*Nn]; // bf16 [p][b][c][n]
__device__ float g_mean[2][Cc];
__device__ float g_rstd[2][Cc];

// ---------------------------------------------------------------------------
// helpers
// ---------------------------------------------------------------------------
__device__ __forceinline__ uint32_t s2u(const void* p){
    return (uint32_t)__cvta_generic_to_shared(p);
}
__device__ __forceinline__ uint32_t packbf(float lo, float hi){
    uint32_t r;
    asm("cvt.rn.bf16x2.f32 %0, %1, %2;" : "=r"(r) : "f"(hi), "f"(lo));
    return r;
}
__device__ __forceinline__ void mma16(float* d, const uint32_t* a, const uint32_t* b){
    asm volatile("mma.sync.aligned.m16n8k16.row.col.f32.bf16.bf16.f32 "
        "{%0,%1,%2,%3}, {%4,%5,%6,%7}, {%8,%9}, {%0,%1,%2,%3};"
        : "+f"(d[0]),"+f"(d[1]),"+f"(d[2]),"+f"(d[3])
        : "r"(a[0]),"r"(a[1]),"r"(a[2]),"r"(a[3]),"r"(b[0]),"r"(b[1]));
}
__device__ __forceinline__ void ldsm4(uint32_t* r, uint32_t addr){
    asm volatile("ldmatrix.sync.aligned.m8n8.x4.shared.b16 {%0,%1,%2,%3}, [%4];"
        : "=r"(r[0]),"=r"(r[1]),"=r"(r[2]),"=r"(r[3]) : "r"(addr));
}
__device__ __forceinline__ void ldsm4t(uint32_t* r, uint32_t addr){
    asm volatile("ldmatrix.sync.aligned.m8n8.x4.trans.shared.b16 {%0,%1,%2,%3}, [%4];"
        : "=r"(r[0]),"=r"(r[1]),"=r"(r[2]),"=r"(r[3]) : "r"(addr));
}
__device__ __forceinline__ void cpa16(uint32_t dst, const void* src){
    asm volatile("cp.async.cg.shared.global [%0], [%1], 16;" :: "r"(dst), "l"(src));
}
#define CP_COMMIT() asm volatile("cp.async.commit_group;")
#define CP_WAIT(N)  asm volatile("cp.async.wait_group %0;" :: "n"(N))

// 64B-row smem tile: swizzled 16B-chunk offset
__device__ __forceinline__ uint32_t sw64(uint32_t tile, int r, int c16){
    return tile + (uint32_t)r*64u + (uint32_t)((c16 ^ ((r>>1)&3))<<4);
}

// ---------------------------------------------------------------------------
// Kernel 1: complex projection (mma.sync bf16), fp32 in, bf16 out [m][c]
// ---------------------------------------------------------------------------
template<int WSEL>
__global__ void __launch_bounds__(256) k_proj(
    const float* __restrict__ xr, const float* __restrict__ xi,
    const float* __restrict__ wr, const float* __restrict__ wi,
    const float* __restrict__ brv, const float* __restrict__ biv)
{
    __nv_bfloat16* yr = (WSEL==0)?g_q[0]:(WSEL==1)?g_k[0]:g_v[0];
    __nv_bfloat16* yi = (WSEL==0)?g_q[1]:(WSEL==1)?g_k[1]:g_v[1];

    __shared__ __nv_bfloat16 sX[2][16][136];   // [part][k][m]
    __shared__ __nv_bfloat16 sW[2][64][24];    // [part][d][k]

    const int tid = threadIdx.x;
    const int w = tid >> 5, lane = tid & 31;
    const int gr = lane >> 2, tg = lane & 3;
    const int wm = w & 3, wn = w >> 2;
    const int m0 = blockIdx.x * 128;
    const int d0 = blockIdx.y * 64;
    const int b  = m0 / Nn;
    const int n0 = m0 - b*Nn;

    const int lp = tid >> 7;
    const int lt = tid & 127;

    float accr[2][4][4], acci[2][4][4];
    #pragma unroll
    for (int mf=0; mf<2; ++mf)
        #pragma unroll
        for (int nf=0; nf<4; ++nf)
            #pragma unroll
            for (int e=0; e<4; ++e){ accr[mf][nf][e]=0.f; acci[mf][nf][e]=0.f; }

    for (int kt = 0; kt < Cc/16; ++kt) {
        const int ck = kt*16;
        const float* xs = lp ? xi : xr;
        const float* ws = lp ? wi : wr;
        #pragma unroll
        for (int it=0; it<4; ++it) {
            int idx = lt + 128*it;
            int c = idx >> 5, nq = idx & 31;
            const float4 v = *(const float4*)(xs + (size_t)b*Cc*Nn + (size_t)(ck+c)*Nn + n0 + nq*4);
            uint2 pk = make_uint2(packbf(v.x,v.y), packbf(v.z,v.w));
            *(uint2*)&sX[lp][c][nq*4] = pk;
        }
        #pragma unroll
        for (int it=0; it<2; ++it) {
            int idx = lt + 128*it;
            int d = idx >> 2, cq = idx & 3;
            const float4 v = *(const float4*)(ws + (size_t)(d0+d)*Cc + ck + cq*4);
            uint2 pk = make_uint2(packbf(v.x,v.y), packbf(v.z,v.w));
            *(uint2*)&sW[lp][d][cq*4] = pk;
        }
        __syncthreads();

        uint32_t axr[2][4], axi[2][4], ain[2][4];
        #pragma unroll
        for (int mf=0; mf<2; ++mf) {
            int rb = wm*32 + mf*16;
            ldsm4t(axr[mf], s2u(&sX[0][(lane&7) + (lane>>4)*8][rb + ((lane>>3)&1)*8]));
            ldsm4t(axi[mf], s2u(&sX[1][(lane&7) + (lane>>4)*8][rb + ((lane>>3)&1)*8]));
            #pragma unroll
            for (int e=0;e<4;++e) ain[mf][e] = axi[mf][e] ^ 0x80008000u;
        }
        #pragma unroll
        for (int nf2=0; nf2<2; ++nf2) {
            int cb = wn*32 + nf2*16;
            uint32_t bwr[4], bwi[4];
            ldsm4(bwr, s2u(&sW[0][cb + (lane>>4)*8 + (lane&7)][((lane>>3)&1)*8]));
            ldsm4(bwi, s2u(&sW[1][cb + (lane>>4)*8 + (lane&7)][((lane>>3)&1)*8]));
            #pragma unroll
            for (int h=0; h<2; ++h) {
                int nfr = nf2*2 + h;
                #pragma unroll
                for (int mf=0; mf<2; ++mf) {
                    mma16(accr[mf][nfr], axr[mf], bwr + 2*h);
                    mma16(accr[mf][nfr], ain[mf], bwi + 2*h);
                    mma16(acci[mf][nfr], axr[mf], bwi + 2*h);
                    mma16(acci[mf][nfr], axi[mf], bwr + 2*h);
                }
            }
        }
        __syncthreads();
    }

    #pragma unroll
    for (int mf=0; mf<2; ++mf) {
        const int row0 = m0 + wm*32 + mf*16 + gr;
        #pragma unroll
        for (int nfr=0; nfr<4; ++nfr) {
            const int col0 = d0 + wn*32 + nfr*8 + 2*tg;
            const float b0r = brv[col0], b1r = brv[col0+1];
            const float b0i = biv[col0], b1i = biv[col0+1];
            *(uint32_t*)&yr[(size_t)row0*Cc + col0]     = packbf(accr[mf][nfr][0]+b0r, accr[mf][nfr][1]+b1r);
            *(uint32_t*)&yr[(size_t)(row0+8)*Cc + col0] = packbf(accr[mf][nfr][2]+b0r, accr[mf][nfr][3]+b1r);
            *(uint32_t*)&yi[(size_t)row0*Cc + col0]     = packbf(acci[mf][nfr][0]+b0i, acci[mf][nfr][1]+b1i);
            *(uint32_t*)&yi[(size_t)(row0+8)*Cc + col0] = packbf(acci[mf][nfr][2]+b0i, acci[mf][nfr][3]+b1i);
        }
    }
}

// ---------------------------------------------------------------------------
// Kernel 2: scores. Block 128n x 256m, warps 2(n)x4(m), warp tile 64x64.
//   3-stage cp.async ring, K-step 32 per stage (both parts). 1 CTA/SM.
//   Stage layout: [Q0 8K | Q1 8K | K0 16K | K1 16K] = 48KB.
// ---------------------------------------------------------------------------
#define SC_STAGE 49152
#define SC_SMEM  (3*SC_STAGE)

__global__ void __launch_bounds__(256, 1) k_scores()
{
    extern __shared__ __align__(16) unsigned char dyn[];
    const uint32_t base = s2u(dyn);

    const int tid = threadIdx.x;
    const int w = tid >> 5, lane = tid & 31;
    const int gr = lane >> 2, tg = lane & 3;
    const int wrow = w & 1, wcol = w >> 1;
    const int m0 = blockIdx.x * 256;
    const int n0 = blockIdx.y * 128;
    const int b  = blockIdx.z;

    const __nv_bfloat16* qp[2] = { g_q[0] + (size_t)b*Nn*Cc, g_q[1] + (size_t)b*Nn*Cc };
    const __nv_bfloat16* kp[2] = { g_k[0] + (size_t)b*Nn*Cc, g_k[1] + (size_t)b*Nn*Cc };

    float acc[4][8][4];
    #pragma unroll
    for (int mf=0; mf<4; ++mf)
        #pragma unroll
        for (int nf=0; nf<8; ++nf)
            #pragma unroll
            for (int e=0; e<4; ++e) acc[mf][nf][e]=0.f;

    auto load_stage = [&](int s, int ck){
        const uint32_t st = base + s*SC_STAGE;
        // Q: 2 parts x 128 rows x 4 chunks = 1024
        #pragma unroll
        for (int it=0; it<4; ++it){
            int idx = tid + 256*it;
            int p = idx >> 9, r = (idx >> 2) & 127, c = idx & 3;
            cpa16(sw64(st + p*8192, r, c), qp[p] + (size_t)(n0+r)*Cc + ck + c*8);
        }
        // K: 2 parts x 256 rows x 4 chunks = 2048
        #pragma unroll
        for (int it=0; it<8; ++it){
            int idx = tid + 256*it;
            int p = idx >> 10, r = (idx >> 2) & 255, c = idx & 3;
            cpa16(sw64(st + 16384 + p*16384, r, c), kp[p] + (size_t)(m0+r)*Cc + ck + c*8);
        }
        CP_COMMIT();
    };

    load_stage(0, 0);
    load_stage(1, 32);

    for (int kt = 0; kt < 8; ++kt) {
        const int s = kt % 3;
        if (kt < 7) { CP_WAIT(1); } else { CP_WAIT(0); }
        __syncthreads();
        if (kt + 2 < 8) load_stage((kt+2)%3, (kt+2)*32);

        const uint32_t st = base + s*SC_STAGE;
        #pragma unroll
        for (int p=0; p<2; ++p) {
            const uint32_t qt = st + p*8192;
            const uint32_t ktile = st + 16384 + p*16384;
            #pragma unroll
            for (int ks=0; ks<32; ks+=16) {
                uint32_t a[4][4];
                #pragma unroll
                for (int mf=0; mf<4; ++mf) {
                    int r = wrow*64 + mf*16 + (lane&15);
                    int c16 = (ks>>3) + (lane>>4);
                    ldsm4(a[mf], sw64(qt, r, c16));
                }
                #pragma unroll
                for (int nf2=0; nf2<4; ++nf2) {
                    int rr = wcol*64 + nf2*16 + (lane>>4)*8 + (lane&7);
                    int c16 = (ks>>3) + ((lane>>3)&1);
                    uint32_t bb[4];
                    ldsm4(bb, sw64(ktile, rr, c16));
                    #pragma unroll
                    for (int mf=0; mf<4; ++mf) {
                        mma16(acc[mf][nf2*2  ], a[mf], bb);
                        mma16(acc[mf][nf2*2+1], a[mf], bb+2);
                    }
                }
            }
        }
        __syncthreads();
    }

    const float sc = 1.0f/16.0f;
    #pragma unroll
    for (int mf=0; mf<4; ++mf) {
        const int row0 = n0 + wrow*64 + mf*16 + gr;
        const size_t r0b = (size_t)b*Nn*Nn + (size_t)row0*Nn;
        const size_t r1b = r0b + (size_t)8*Nn;
        #pragma unroll
        for (int nfr=0; nfr<8; ++nfr) {
            const int col0 = m0 + wcol*64 + nfr*8 + 2*tg;
            *(uint32_t*)&g_attn[r0b + col0] = packbf(acc[mf][nfr][0]*sc, acc[mf][nfr][1]*sc);
            *(uint32_t*)&g_attn[r1b + col0] = packbf(acc[mf][nfr][2]*sc, acc[mf][nfr][3]*sc);
        }
    }
}

// ---------------------------------------------------------------------------
// Kernel 3: softmax — no max subtraction (logits bounded |v| <~ 16, safe in
//   fp32: exp<=9e6, row sum <= 2e10). bf16 in/out. One reduction round.
// ---------------------------------------------------------------------------
__global__ void __launch_bounds__(384) k_softmax()
{
    const size_t rowbase = (size_t)blockIdx.x * Nn;
    const __nv_bfloat162* src = (const __nv_bfloat162*)(g_attn + rowbase);
    __nv_bfloat162* dst = (__nv_bfloat162*)(g_attnb + rowbase);
    const int tid = threadIdx.x;
    const int wid = tid >> 5, lane = tid & 31;

    __shared__ float sred[12];
    __shared__ float sbc;

    float v[6];
    #pragma unroll
    for (int i=0;i<3;++i){
        float2 f = __bfloat1622float2(src[tid + 384*i]);
        v[2*i] = __expf(f.x); v[2*i+1] = __expf(f.y);
    }
    float sum = 0.f;
    #pragma unroll
    for (int i=0;i<6;++i) sum += v[i];
    #pragma unroll
    for (int off=16; off>0; off>>=1) sum += __shfl_xor_sync(0xFFFFFFFFu, sum, off);
    if (lane==0) sred[wid] = sum;
    __syncthreads();
    if (wid==0){
        float s2 = (lane<12) ? sred[lane] : 0.f;
        #pragma unroll
        for (int off=8; off>0; off>>=1) s2 += __shfl_xor_sync(0xFFFFFFFFu, s2, off);
        if (lane==0) sbc = s2;
    }
    __syncthreads();
    const float inv = 1.f / sbc;

    #pragma unroll
    for (int i=0;i<3;++i)
        dst[tid + 384*i] = __float22bfloat162_rn(make_float2(v[2*i]*inv, v[2*i+1]*inv));
}

// ---------------------------------------------------------------------------
// Kernel 4: AV. Block 128n x 64d, warps 4(n)x2(d). 4-stage ring, K-step 32.
//   Output bf16 [d][n] via smem transpose stage.
// ---------------------------------------------------------------------------
#define AV_STAGE 17408
#define AV_SMEM  (4*AV_STAGE)

__global__ void __launch_bounds__(256) k_av()
{
    extern __shared__ __align__(16) unsigned char dyn[];
    const uint32_t base = s2u(dyn);

    const int tid = threadIdx.x;
    const int w = tid >> 5, lane = tid & 31;
    const int gr = lane >> 2, tg = lane & 3;
    const int wm = w & 3, wn = w >> 2;
    const int n0 = blockIdx.x * 128;
    const int d0 = blockIdx.y * 64;
    const int b  = blockIdx.z;

    const __nv_bfloat16* Ab  = g_attnb + (size_t)b*Nn*Nn;
    const __nv_bfloat16* vp[2] = { g_v[0] + (size_t)b*Nn*Cc, g_v[1] + (size_t)b*Nn*Cc };

    float accr[2][4][4], acci[2][4][4];
    #pragma unroll
    for (int mf=0; mf<2; ++mf)
        #pragma unroll
        for (int nf=0; nf<4; ++nf)
            #pragma unroll
            for (int e=0; e<4; ++e){ accr[mf][nf][e]=0.f; acci[mf][nf][e]=0.f; }

    auto load_stage = [&](int s, int mk){
        const uint32_t st = base + s*AV_STAGE;
        #pragma unroll
        for (int it=0; it<2; ++it){
            int idx = tid + 256*it;
            int r = idx>>2, c = idx&3;
            cpa16(sw64(st, r, c), Ab + (size_t)(n0+r)*Nn + mk + c*8);
        }
        #pragma unroll
        for (int it=0; it<2; ++it){
            int idx = tid + 256*it;
            int p = idx>>8, r = (idx>>3)&31, c = idx&7;
            cpa16(st + 8192 + p*4608 + r*144 + c*16,
                  vp[p] + (size_t)(mk+r)*Cc + d0 + c*8);
        }
        CP_COMMIT();
    };

    load_stage(0, 0);
    load_stage(1, 32);
    load_stage(2, 64);

    const int NKT = Nn/32;   // 72
    for (int kt = 0; kt < NKT; ++kt) {
        const int s = kt & 3;
        if (kt < NKT-2)      { CP_WAIT(2); }
        else if (kt == NKT-2){ CP_WAIT(1); }
        else                 { CP_WAIT(0); }
        __syncthreads();
        if (kt + 3 < NKT) load_stage((kt+3)&3, (kt+3)*32);

        const uint32_t st = base + s*AV_STAGE;
        #pragma unroll
        for (int ks=0; ks<32; ks+=16) {
            uint32_t a[2][4];
            #pragma unroll
            for (int mf=0; mf<2; ++mf) {
                int r = wm*32 + mf*16 + (lane&15);
                int c16 = (ks>>3) + (lane>>4);
                ldsm4(a[mf], sw64(st, r, c16));
            }
            #pragma unroll
            for (int nf2=0; nf2<2; ++nf2) {
                int cb = wn*32 + nf2*16;
                uint32_t bvr[4], bvi[4];
                uint32_t vaddr = st + 8192 + (uint32_t)(ks + (lane&15))*144 + (uint32_t)(cb + (lane>>4)*8)*2;
                ldsm4t(bvr, vaddr);
                ldsm4t(bvi, vaddr + 4608);
                #pragma unroll
                for (int h=0; h<2; ++h) {
                    int nfr = nf2*2 + h;
                    #pragma unroll
                    for (int mf=0; mf<2; ++mf) {
                        mma16(accr[mf][nfr], a[mf], bvr + 2*h);
                        mma16(acci[mf][nfr], a[mf], bvi + 2*h);
                    }
                }
            }
        }
        __syncthreads();
    }

    // transpose epilogue -> g_outT [d][n] bf16 (smem reuse)
    __nv_bfloat16 (*stage)[144] = (__nv_bfloat16(*)[144])dyn;
    const size_t basep = (size_t)b*Cc*Nn + (size_t)d0*Nn + n0;
    #pragma unroll
    for (int p=0; p<2; ++p) {
        __syncthreads();
        #pragma unroll
        for (int mf=0; mf<2; ++mf) {
            int rl = wm*32 + mf*16 + gr;
            #pragma unroll
            for (int nfr=0; nfr<4; ++nfr) {
                int cl = wn*32 + nfr*8 + 2*tg;
                float* acc = p ? acci[mf][nfr] : accr[mf][nfr];
                stage[cl  ][rl  ] = __float2bfloat16(acc[0]);
                stage[cl+1][rl  ] = __float2bfloat16(acc[1]);
                stage[cl  ][rl+8] = __float2bfloat16(acc[2]);
                stage[cl+1][rl+8] = __float2bfloat16(acc[3]);
            }
        }
        __syncthreads();
        #pragma unroll
        for (int it=0; it<4; ++it) {
            int idx = tid + 256*it;
            int dl = idx >> 4, c8 = idx & 15;
            *(uint4*)(g_outT[p] + basep + (size_t)dl*Nn + c8*8) = *(const uint4*)&stage[dl][c8*8];
        }
    }
}

// ---------------------------------------------------------------------------
// Kernel 5/6: BatchNorm (bf16 outT, vectorized)
// ---------------------------------------------------------------------------
__global__ void __launch_bounds__(256) k_bnstats(
    const float* __restrict__ xr, const float* __restrict__ xi,
    const float* __restrict__ gamma)
{
    const int c = blockIdx.x, p = blockIdx.y;
    const int tid = threadIdx.x;
    const float* x = p ? xi : xr;
    const __nv_bfloat16* o = g_outT[p];
    const float g = gamma[0];

    float s = 0.f, ss = 0.f;
    for (int b = 0; b < Bb; ++b) {
        const size_t bb = (size_t)b*Cc*Nn + (size_t)c*Nn;
        for (int n4 = tid; n4 < Nn/4; n4 += 256) {
            float4 xv = *(const float4*)(x + bb + n4*4);
            uint2 ou = *(const uint2*)(o + bb + n4*4);
            float2 o01 = __bfloat1622float2(*reinterpret_cast<const __nv_bfloat162*>(&ou.x));
            float2 o23 = __bfloat1622float2(*reinterpret_cast<const __nv_bfloat162*>(&ou.y));
            float z0 = xv.x + g*o01.x, z1 = xv.y + g*o01.y;
            float z2 = xv.z + g*o23.x, z3 = xv.w + g*o23.y;
            s  += z0+z1+z2+z3;
            ss += z0*z0+z1*z1+z2*z2+z3*z3;
        }
    }
    __shared__ float rs[256], rss[256];
    rs[tid] = s; rss[tid] = ss; __syncthreads();
    #pragma unroll
    for (int st = 128; st > 0; st >>= 1) {
        if (tid < st) { rs[tid] += rs[tid+st]; rss[tid] += rss[tid+st]; }
        __syncthreads();
    }
    if (tid == 0) {
        const float inv_cnt = 1.f / (float)Mtot;
        float mean = rs[0] * inv_cnt;
        float var  = rss[0] * inv_cnt - mean*mean;
        g_mean[p][c] = mean;
        g_rstd[p][c] = rsqrtf(var + EPSf);
    }
}

__global__ void __launch_bounds__(256) k_bnapply(
    const float* __restrict__ xr, const float* __restrict__ xi,
    const float* __restrict__ gamma,
    const float* __restrict__ bnwr, const float* __restrict__ bnbr,
    const float* __restrict__ bnwi, const float* __restrict__ bnbi,
    float* __restrict__ out)
{
    const int idx4 = blockIdx.x*256 + threadIdx.x;
    const size_t e = (size_t)idx4 * 4;
    const size_t half = (size_t)Bb*Cc*Nn;
    const int p = (e >= half) ? 1 : 0;
    const size_t rem = e - (size_t)p*half;
    const int c = (int)((rem / Nn) % Cc);

    const float* x = p ? xi : xr;
    const float g = gamma[0];
    const float wsc = (p ? bnwi[c] : bnwr[c]) * g_rstd[p][c];
    const float bia = (p ? bnbi[c] : bnbr[c]);
    const float mu = g_mean[p][c];

    float4 xv = *(const float4*)(x + rem);
    uint2 ou = *(const uint2*)(g_outT[p] + rem);
    float2 o01 = __bfloat1622float2(*reinterpret_cast<const __nv_bfloat162*>(&ou.x));
    float2 o23 = __bfloat1622float2(*reinterpret_cast<const __nv_bfloat162*>(&ou.y));

    float4 r;
    r.x = (xv.x + g*o01.x - mu) * wsc + bia;
    r.y = (xv.y + g*o01.y - mu) * wsc + bia;
    r.z = (xv.z + g*o23.x - mu) * wsc + bia;
    r.w = (xv.w + g*o23.y - mu) * wsc + bia;
    *(float4*)(out + e) = r;
}

// ---------------------------------------------------------------------------
// Launch
// ---------------------------------------------------------------------------
extern "C" void kernel_launch(void* const* d_in, const int* in_sizes, int n_in,
                              void* d_out, int out_size)
{
    const float* xr   = (const float*)d_in[0];
    const float* xi   = (const float*)d_in[1];
    const float* q_wr = (const float*)d_in[2];
    const float* q_wi = (const float*)d_in[3];
    const float* q_br = (const float*)d_in[4];
    const float* q_bi = (const float*)d_in[5];
    const float* k_wr = (const float*)d_in[6];
    const float* k_wi = (const float*)d_in[7];
    const float* k_br = (const float*)d_in[8];
    const float* k_bi = (const float*)d_in[9];
    const float* v_wr = (const float*)d_in[10];
    const float* v_wi = (const float*)d_in[11];
    const float* v_br = (const float*)d_in[12];
    const float* v_bi = (const float*)d_in[13];
    const float* gamma= (const float*)d_in[14];
    const float* bnwr = (const float*)d_in[15];
    const float* bnbr = (const float*)d_in[16];
    const float* bnwi = (const float*)d_in[17];
    const float* bnbi = (const float*)d_in[18];
    float* out = (float*)d_out;

    cudaFuncSetAttribute(k_scores, cudaFuncAttributeMaxDynamicSharedMemorySize, SC_SMEM);
    cudaFuncSetAttribute(k_av,     cudaFuncAttributeMaxDynamicSharedMemorySize, AV_SMEM);

    k_proj<0><<<dim3(Mtot/128, Cc/64), 256>>>(xr, xi, q_wr, q_wi, q_br, q_bi);
    k_proj<1><<<dim3(Mtot/128, Cc/64), 256>>>(xr, xi, k_wr, k_wi, k_br, k_bi);
    k_proj<2><<<dim3(Mtot/128, Cc/64), 256>>>(xr, xi, v_wr, v_wi, v_br, v_bi);

    k_scores<<<dim3(Nn/256, Nn/128, Bb), 256, SC_SMEM>>>();
    k_softmax<<<Mtot, 384>>>();
    k_av<<<dim3(Nn/128, Cc/64, Bb), 256, AV_SMEM>>>();

    k_bnstats<<<dim3(Cc, 2), 256>>>(xr, xi, gamma);
    k_bnapply<<<(2*(size_t)Bb*Cc*Nn/4)/256, 256>>>(xr, xi, gamma, bnwr, bnbr, bnwi, bnbi, out);
}

// round 8
// speedup vs baseline: 1.0928x; 1.0928x over previous
#include <cuda_runtime.h>
#include <cuda_bf16.h>
#include <math.h>
#include <stdint.h>

#define Bb   8
#define Cc   256
#define Nn   2304
#define Mtot (Bb*Nn)
#define NMB  (Nn/128)      // 18 m-blocks per row
#define EPSf 1e-5f

// ---------------------------------------------------------------------------
// Scratch
// ---------------------------------------------------------------------------
__device__ __align__(128) __nv_bfloat16 g_q[2][(size_t)Mtot*Cc];
__device__ __align__(128) __nv_bfloat16 g_k[2][(size_t)Mtot*Cc];
__device__ __align__(128) __nv_bfloat16 g_v[2][(size_t)Mtot*Cc];
__device__ __align__(128) __nv_bfloat16 g_attnb[(size_t)Bb*Nn*Nn];   // bf16 exp(S) (unnormalized)
__device__ __align__(128) float g_psum[(size_t)Bb*NMB*Nn];           // partial row sums
__device__ __align__(128) float g_rinv[(size_t)Mtot];                // 1/rowsum
__device__ __align__(128) __nv_bfloat16 g_outT[2][(size_t)Bb*Cc*Nn]; // bf16 [p][b][c][n]
__device__ float g_mean[2][Cc];
__device__ float g_rstd[2][Cc];

// ---------------------------------------------------------------------------
// helpers
// ---------------------------------------------------------------------------
__device__ __forceinline__ uint32_t s2u(const void* p){
    return (uint32_t)__cvta_generic_to_shared(p);
}
__device__ __forceinline__ uint32_t packbf(float lo, float hi){
    uint32_t r;
    asm("cvt.rn.bf16x2.f32 %0, %1, %2;" : "=r"(r) : "f"(hi), "f"(lo));
    return r;
}
__device__ __forceinline__ void mma16(float* d, const uint32_t* a, const uint32_t* b){
    asm volatile("mma.sync.aligned.m16n8k16.row.col.f32.bf16.bf16.f32 "
        "{%0,%1,%2,%3}, {%4,%5,%6,%7}, {%8,%9}, {%0,%1,%2,%3};"
        : "+f"(d[0]),"+f"(d[1]),"+f"(d[2]),"+f"(d[3])
        : "r"(a[0]),"r"(a[1]),"r"(a[2]),"r"(a[3]),"r"(b[0]),"r"(b[1]));
}
__device__ __forceinline__ void ldsm4(uint32_t* r, uint32_t addr){
    asm volatile("ldmatrix.sync.aligned.m8n8.x4.shared.b16 {%0,%1,%2,%3}, [%4];"
        : "=r"(r[0]),"=r"(r[1]),"=r"(r[2]),"=r"(r[3]) : "r"(addr));
}
__device__ __forceinline__ void ldsm4t(uint32_t* r, uint32_t addr){
    asm volatile("ldmatrix.sync.aligned.m8n8.x4.trans.shared.b16 {%0,%1,%2,%3}, [%4];"
        : "=r"(r[0]),"=r"(r[1]),"=r"(r[2]),"=r"(r[3]) : "r"(addr));
}
__device__ __forceinline__ void cpa16(uint32_t dst, const void* src){
    asm volatile("cp.async.cg.shared.global [%0], [%1], 16;" :: "r"(dst), "l"(src));
}
#define CP_COMMIT() asm volatile("cp.async.commit_group;")
#define CP_WAIT(N)  asm volatile("cp.async.wait_group %0;" :: "n"(N))

// 64B-row smem tile: swizzled 16B-chunk offset
__device__ __forceinline__ uint32_t sw64(uint32_t tile, int r, int c16){
    return tile + (uint32_t)r*64u + (uint32_t)((c16 ^ ((r>>1)&3))<<4);
}

// ---------------------------------------------------------------------------
// Kernel 1: complex projection (mma.sync bf16), fp32 in, bf16 out [m][c]
// ---------------------------------------------------------------------------
template<int WSEL>
__global__ void __launch_bounds__(256) k_proj(
    const float* __restrict__ xr, const float* __restrict__ xi,
    const float* __restrict__ wr, const float* __restrict__ wi,
    const float* __restrict__ brv, const float* __restrict__ biv)
{
    __nv_bfloat16* yr = (WSEL==0)?g_q[0]:(WSEL==1)?g_k[0]:g_v[0];
    __nv_bfloat16* yi = (WSEL==0)?g_q[1]:(WSEL==1)?g_k[1]:g_v[1];

    __shared__ __nv_bfloat16 sX[2][16][136];   // [part][k][m]
    __shared__ __nv_bfloat16 sW[2][64][24];    // [part][d][k]

    const int tid = threadIdx.x;
    const int w = tid >> 5, lane = tid & 31;
    const int gr = lane >> 2, tg = lane & 3;
    const int wm = w & 3, wn = w >> 2;
    const int m0 = blockIdx.x * 128;
    const int d0 = blockIdx.y * 64;
    const int b  = m0 / Nn;
    const int n0 = m0 - b*Nn;

    const int lp = tid >> 7;
    const int lt = tid & 127;

    float accr[2][4][4], acci[2][4][4];
    #pragma unroll
    for (int mf=0; mf<2; ++mf)
        #pragma unroll
        for (int nf=0; nf<4; ++nf)
            #pragma unroll
            for (int e=0; e<4; ++e){ accr[mf][nf][e]=0.f; acci[mf][nf][e]=0.f; }

    for (int kt = 0; kt < Cc/16; ++kt) {
        const int ck = kt*16;
        const float* xs = lp ? xi : xr;
        const float* ws = lp ? wi : wr;
        #pragma unroll
        for (int it=0; it<4; ++it) {
            int idx = lt + 128*it;
            int c = idx >> 5, nq = idx & 31;
            const float4 v = *(const float4*)(xs + (size_t)b*Cc*Nn + (size_t)(ck+c)*Nn + n0 + nq*4);
            uint2 pk = make_uint2(packbf(v.x,v.y), packbf(v.z,v.w));
            *(uint2*)&sX[lp][c][nq*4] = pk;
        }
        #pragma unroll
        for (int it=0; it<2; ++it) {
            int idx = lt + 128*it;
            int d = idx >> 2, cq = idx & 3;
            const float4 v = *(const float4*)(ws + (size_t)(d0+d)*Cc + ck + cq*4);
            uint2 pk = make_uint2(packbf(v.x,v.y), packbf(v.z,v.w));
            *(uint2*)&sW[lp][d][cq*4] = pk;
        }
        __syncthreads();

        uint32_t axr[2][4], axi[2][4], ain[2][4];
        #pragma unroll
        for (int mf=0; mf<2; ++mf) {
            int rb = wm*32 + mf*16;
            ldsm4t(axr[mf], s2u(&sX[0][(lane&7) + (lane>>4)*8][rb + ((lane>>3)&1)*8]));
            ldsm4t(axi[mf], s2u(&sX[1][(lane&7) + (lane>>4)*8][rb + ((lane>>3)&1)*8]));
            #pragma unroll
            for (int e=0;e<4;++e) ain[mf][e] = axi[mf][e] ^ 0x80008000u;
        }
        #pragma unroll
        for (int nf2=0; nf2<2; ++nf2) {
            int cb = wn*32 + nf2*16;
            uint32_t bwr[4], bwi[4];
            ldsm4(bwr, s2u(&sW[0][cb + (lane>>4)*8 + (lane&7)][((lane>>3)&1)*8]));
            ldsm4(bwi, s2u(&sW[1][cb + (lane>>4)*8 + (lane&7)][((lane>>3)&1)*8]));
            #pragma unroll
            for (int h=0; h<2; ++h) {
                int nfr = nf2*2 + h;
                #pragma unroll
                for (int mf=0; mf<2; ++mf) {
                    mma16(accr[mf][nfr], axr[mf], bwr + 2*h);
                    mma16(accr[mf][nfr], ain[mf], bwi + 2*h);
                    mma16(acci[mf][nfr], axr[mf], bwi + 2*h);
                    mma16(acci[mf][nfr], axi[mf], bwr + 2*h);
                }
            }
        }
        __syncthreads();
    }

    #pragma unroll
    for (int mf=0; mf<2; ++mf) {
        const int row0 = m0 + wm*32 + mf*16 + gr;
        #pragma unroll
        for (int nfr=0; nfr<4; ++nfr) {
            const int col0 = d0 + wn*32 + nfr*8 + 2*tg;
            const float b0r = brv[col0], b1r = brv[col0+1];
            const float b0i = biv[col0], b1i = biv[col0+1];
            *(uint32_t*)&yr[(size_t)row0*Cc + col0]     = packbf(accr[mf][nfr][0]+b0r, accr[mf][nfr][1]+b1r);
            *(uint32_t*)&yr[(size_t)(row0+8)*Cc + col0] = packbf(accr[mf][nfr][2]+b0r, accr[mf][nfr][3]+b1r);
            *(uint32_t*)&yi[(size_t)row0*Cc + col0]     = packbf(acci[mf][nfr][0]+b0i, acci[mf][nfr][1]+b1i);
            *(uint32_t*)&yi[(size_t)(row0+8)*Cc + col0] = packbf(acci[mf][nfr][2]+b0i, acci[mf][nfr][3]+b1i);
        }
    }
}

// ---------------------------------------------------------------------------
// Kernel 2: scores + exp. Block 128n x 128m, warps 2(n)x4(m), warp 64x32.
//   3-stage ring, K-step 32. Epilogue: exp(s/16) -> bf16 g_attnb +
//   deterministic per-block partial row sums -> g_psum.
// ---------------------------------------------------------------------------
#define SC_STAGE 32768
#define SC_SMEM  (3*SC_STAGE)

__global__ void __launch_bounds__(256) k_scores()
{
    extern __shared__ __align__(16) unsigned char dyn[];
    const uint32_t base = s2u(dyn);

    const int tid = threadIdx.x;
    const int w = tid >> 5, lane = tid & 31;
    const int gr = lane >> 2, tg = lane & 3;
    const int wrow = w & 1, wcol = w >> 1;
    const int m0 = blockIdx.x * 128;
    const int n0 = blockIdx.y * 128;
    const int b  = blockIdx.z;

    const __nv_bfloat16* srcs[4] = {
        g_q[0] + (size_t)b*Nn*Cc, g_q[1] + (size_t)b*Nn*Cc,
        g_k[0] + (size_t)b*Nn*Cc, g_k[1] + (size_t)b*Nn*Cc };
    const int rbase[4] = { n0, n0, m0, m0 };

    float acc[4][4][4];
    #pragma unroll
    for (int mf=0; mf<4; ++mf)
        #pragma unroll
        for (int nf=0; nf<4; ++nf)
            #pragma unroll
            for (int e=0; e<4; ++e) acc[mf][nf][e]=0.f;

    auto load_stage = [&](int s, int ck){
        const uint32_t st = base + s*SC_STAGE;
        #pragma unroll
        for (int t=0;t<4;++t){
            const uint32_t tb = st + t*8192;
            #pragma unroll
            for (int it=0; it<2; ++it){
                int idx = tid + 256*it;
                int r = idx>>2, c = idx&3;
                cpa16(sw64(tb, r, c), srcs[t] + (size_t)(rbase[t]+r)*Cc + ck + c*8);
            }
        }
        CP_COMMIT();
    };

    load_stage(0, 0);
    load_stage(1, 32);

    for (int kt = 0; kt < 8; ++kt) {
        const int s = kt % 3;
        if (kt < 7) { CP_WAIT(1); } else { CP_WAIT(0); }
        __syncthreads();
        if (kt + 2 < 8) load_stage((kt+2)%3, (kt+2)*32);

        const uint32_t st = base + s*SC_STAGE;
        #pragma unroll
        for (int p=0; p<2; ++p) {
            const uint32_t qt = st + p*8192;
            const uint32_t ktile = st + 16384 + p*8192;
            #pragma unroll
            for (int ks=0; ks<32; ks+=16) {
                uint32_t a[4][4];
                #pragma unroll
                for (int mf=0; mf<4; ++mf) {
                    int r = wrow*64 + mf*16 + (lane&15);
                    int c16 = (ks>>3) + (lane>>4);
                    ldsm4(a[mf], sw64(qt, r, c16));
                }
                #pragma unroll
                for (int nf2=0; nf2<2; ++nf2) {
                    int rr = wcol*32 + nf2*16 + (lane>>4)*8 + (lane&7);
                    int c16 = (ks>>3) + ((lane>>3)&1);
                    uint32_t bb[4];
                    ldsm4(bb, sw64(ktile, rr, c16));
                    #pragma unroll
                    for (int mf=0; mf<4; ++mf) {
                        mma16(acc[mf][nf2*2  ], a[mf], bb);
                        mma16(acc[mf][nf2*2+1], a[mf], bb+2);
                    }
                }
            }
        }
        __syncthreads();
    }

    // epilogue: exp + store + deterministic partial row sums
    float (*spsum)[128] = (float(*)[128])dyn;   // [wcol][row_local], 2KB
    const float sc = 1.0f/16.0f;
    #pragma unroll
    for (int mf=0; mf<4; ++mf) {
        const int row0 = n0 + wrow*64 + mf*16 + gr;
        const size_t r0b = (size_t)b*Nn*Nn + (size_t)row0*Nn;
        const size_t r1b = r0b + (size_t)8*Nn;
        float p0 = 0.f, p1 = 0.f;
        #pragma unroll
        for (int nfr=0; nfr<4; ++nfr) {
            const int col0 = m0 + wcol*32 + nfr*8 + 2*tg;
            float e0 = __expf(acc[mf][nfr][0]*sc);
            float e1 = __expf(acc[mf][nfr][1]*sc);
            float e2 = __expf(acc[mf][nfr][2]*sc);
            float e3 = __expf(acc[mf][nfr][3]*sc);
            *(uint32_t*)&g_attnb[r0b + col0] = packbf(e0, e1);
            *(uint32_t*)&g_attnb[r1b + col0] = packbf(e2, e3);
            p0 += e0 + e1;
            p1 += e2 + e3;
        }
        // reduce over the 4 tg lanes (lanes gr*4 + tg)
        p0 += __shfl_xor_sync(0xFFFFFFFFu, p0, 1);
        p0 += __shfl_xor_sync(0xFFFFFFFFu, p0, 2);
        p1 += __shfl_xor_sync(0xFFFFFFFFu, p1, 1);
        p1 += __shfl_xor_sync(0xFFFFFFFFu, p1, 2);
        if (tg == 0) {
            spsum[wcol][wrow*64 + mf*16 + gr    ] = p0;
            spsum[wcol][wrow*64 + mf*16 + gr + 8] = p1;
        }
    }
    __syncthreads();
    if (tid < 128) {
        float s4 = spsum[0][tid] + spsum[1][tid] + spsum[2][tid] + spsum[3][tid];
        g_psum[((size_t)b*NMB + (m0>>7))*Nn + n0 + tid] = s4;
    }
}

// ---------------------------------------------------------------------------
// Kernel 3: row-sum reduce -> 1/sum
// ---------------------------------------------------------------------------
__global__ void __launch_bounds__(256) k_rowsum()
{
    const int i = blockIdx.x*256 + threadIdx.x;   // b*Nn + n
    const int b = i / Nn, n = i - b*Nn;
    float s = 0.f;
    #pragma unroll
    for (int mb=0; mb<NMB; ++mb)
        s += g_psum[((size_t)b*NMB + mb)*Nn + n];
    g_rinv[i] = 1.f / s;
}

// ---------------------------------------------------------------------------
// Kernel 4: AV. Block 128n x 64d, warps 4(n)x2(d). 4-stage ring, K-step 32.
//   A = unnormalized exp; epilogue scales by g_rinv[n]. Output bf16 [d][n].
// ---------------------------------------------------------------------------
#define AV_STAGE 17408
#define AV_SMEM  (4*AV_STAGE)

__global__ void __launch_bounds__(256) k_av()
{
    extern __shared__ __align__(16) unsigned char dyn[];
    const uint32_t base = s2u(dyn);

    const int tid = threadIdx.x;
    const int w = tid >> 5, lane = tid & 31;
    const int gr = lane >> 2, tg = lane & 3;
    const int wm = w & 3, wn = w >> 2;
    const int n0 = blockIdx.x * 128;
    const int d0 = blockIdx.y * 64;
    const int b  = blockIdx.z;

    const __nv_bfloat16* Ab  = g_attnb + (size_t)b*Nn*Nn;
    const __nv_bfloat16* vp[2] = { g_v[0] + (size_t)b*Nn*Cc, g_v[1] + (size_t)b*Nn*Cc };

    float accr[2][4][4], acci[2][4][4];
    #pragma unroll
    for (int mf=0; mf<2; ++mf)
        #pragma unroll
        for (int nf=0; nf<4; ++nf)
            #pragma unroll
            for (int e=0; e<4; ++e){ accr[mf][nf][e]=0.f; acci[mf][nf][e]=0.f; }

    auto load_stage = [&](int s, int mk){
        const uint32_t st = base + s*AV_STAGE;
        #pragma unroll
        for (int it=0; it<2; ++it){
            int idx = tid + 256*it;
            int r = idx>>2, c = idx&3;
            cpa16(sw64(st, r, c), Ab + (size_t)(n0+r)*Nn + mk + c*8);
        }
        #pragma unroll
        for (int it=0; it<2; ++it){
            int idx = tid + 256*it;
            int p = idx>>8, r = (idx>>3)&31, c = idx&7;
            cpa16(st + 8192 + p*4608 + r*144 + c*16,
                  vp[p] + (size_t)(mk+r)*Cc + d0 + c*8);
        }
        CP_COMMIT();
    };

    load_stage(0, 0);
    load_stage(1, 32);
    load_stage(2, 64);

    const int NKT = Nn/32;   // 72
    for (int kt = 0; kt < NKT; ++kt) {
        const int s = kt & 3;
        if (kt < NKT-2)      { CP_WAIT(2); }
        else if (kt == NKT-2){ CP_WAIT(1); }
        else                 { CP_WAIT(0); }
        __syncthreads();
        if (kt + 3 < NKT) load_stage((kt+3)&3, (kt+3)*32);

        const uint32_t st = base + s*AV_STAGE;
        #pragma unroll
        for (int ks=0; ks<32; ks+=16) {
            uint32_t a[2][4];
            #pragma unroll
            for (int mf=0; mf<2; ++mf) {
                int r = wm*32 + mf*16 + (lane&15);
                int c16 = (ks>>3) + (lane>>4);
                ldsm4(a[mf], sw64(st, r, c16));
            }
            #pragma unroll
            for (int nf2=0; nf2<2; ++nf2) {
                int cb = wn*32 + nf2*16;
                uint32_t bvr[4], bvi[4];
                uint32_t vaddr = st + 8192 + (uint32_t)(ks + (lane&15))*144 + (uint32_t)(cb + (lane>>4)*8)*2;
                ldsm4t(bvr, vaddr);
                ldsm4t(bvi, vaddr + 4608);
                #pragma unroll
                for (int h=0; h<2; ++h) {
                    int nfr = nf2*2 + h;
                    #pragma unroll
                    for (int mf=0; mf<2; ++mf) {
                        mma16(accr[mf][nfr], a[mf], bvr + 2*h);
                        mma16(acci[mf][nfr], a[mf], bvi + 2*h);
                    }
                }
            }
        }
        __syncthreads();
    }

    // normalization factors for this thread's rows
    float rin[2][2];
    #pragma unroll
    for (int mf=0; mf<2; ++mf) {
        rin[mf][0] = g_rinv[(size_t)b*Nn + n0 + wm*32 + mf*16 + gr];
        rin[mf][1] = g_rinv[(size_t)b*Nn + n0 + wm*32 + mf*16 + gr + 8];
    }

    // transpose epilogue -> g_outT [d][n] bf16 (smem reuse)
    __nv_bfloat16 (*stage)[144] = (__nv_bfloat16(*)[144])dyn;
    const size_t basep = (size_t)b*Cc*Nn + (size_t)d0*Nn + n0;
    #pragma unroll
    for (int p=0; p<2; ++p) {
        __syncthreads();
        #pragma unroll
        for (int mf=0; mf<2; ++mf) {
            int rl = wm*32 + mf*16 + gr;
            #pragma unroll
            for (int nfr=0; nfr<4; ++nfr) {
                int cl = wn*32 + nfr*8 + 2*tg;
                float* acc = p ? acci[mf][nfr] : accr[mf][nfr];
                stage[cl  ][rl  ] = __float2bfloat16(acc[0]*rin[mf][0]);
                stage[cl+1][rl  ] = __float2bfloat16(acc[1]*rin[mf][0]);
                stage[cl  ][rl+8] = __float2bfloat16(acc[2]*rin[mf][1]);
                stage[cl+1][rl+8] = __float2bfloat16(acc[3]*rin[mf][1]);
            }
        }
        __syncthreads();
        #pragma unroll
        for (int it=0; it<4; ++it) {
            int idx = tid + 256*it;
            int dl = idx >> 4, c8 = idx & 15;
            *(uint4*)(g_outT[p] + basep + (size_t)dl*Nn + c8*8) = *(const uint4*)&stage[dl][c8*8];
        }
    }
}

// ---------------------------------------------------------------------------
// Kernel 5/6: BatchNorm (bf16 outT, vectorized)
// ---------------------------------------------------------------------------
__global__ void __launch_bounds__(256) k_bnstats(
    const float* __restrict__ xr, const float* __restrict__ xi,
    const float* __restrict__ gamma)
{
    const int c = blockIdx.x, p = blockIdx.y;
    const int tid = threadIdx.x;
    const float* x = p ? xi : xr;
    const __nv_bfloat16* o = g_outT[p];
    const float g = gamma[0];

    float s = 0.f, ss = 0.f;
    for (int b = 0; b < Bb; ++b) {
        const size_t bb = (size_t)b*Cc*Nn + (size_t)c*Nn;
        for (int n4 = tid; n4 < Nn/4; n4 += 256) {
            float4 xv = *(const float4*)(x + bb + n4*4);
            uint2 ou = *(const uint2*)(o + bb + n4*4);
            float2 o01 = __bfloat1622float2(*reinterpret_cast<const __nv_bfloat162*>(&ou.x));
            float2 o23 = __bfloat1622float2(*reinterpret_cast<const __nv_bfloat162*>(&ou.y));
            float z0 = xv.x + g*o01.x, z1 = xv.y + g*o01.y;
            float z2 = xv.z + g*o23.x, z3 = xv.w + g*o23.y;
            s  += z0+z1+z2+z3;
            ss += z0*z0+z1*z1+z2*z2+z3*z3;
        }
    }
    __shared__ float rs[256], rss[256];
    rs[tid] = s; rss[tid] = ss; __syncthreads();
    #pragma unroll
    for (int st = 128; st > 0; st >>= 1) {
        if (tid < st) { rs[tid] += rs[tid+st]; rss[tid] += rss[tid+st]; }
        __syncthreads();
    }
    if (tid == 0) {
        const float inv_cnt = 1.f / (float)Mtot;
        float mean = rs[0] * inv_cnt;
        float var  = rss[0] * inv_cnt - mean*mean;
        g_mean[p][c] = mean;
        g_rstd[p][c] = rsqrtf(var + EPSf);
    }
}

__global__ void __launch_bounds__(256) k_bnapply(
    const float* __restrict__ xr, const float* __restrict__ xi,
    const float* __restrict__ gamma,
    const float* __restrict__ bnwr, const float* __restrict__ bnbr,
    const float* __restrict__ bnwi, const float* __restrict__ bnbi,
    float* __restrict__ out)
{
    const int idx4 = blockIdx.x*256 + threadIdx.x;
    const size_t e = (size_t)idx4 * 4;
    const size_t half = (size_t)Bb*Cc*Nn;
    const int p = (e >= half) ? 1 : 0;
    const size_t rem = e - (size_t)p*half;
    const int c = (int)((rem / Nn) % Cc);

    const float* x = p ? xi : xr;
    const float g = gamma[0];
    const float wsc = (p ? bnwi[c] : bnwr[c]) * g_rstd[p][c];
    const float bia = (p ? bnbi[c] : bnbr[c]);
    const float mu = g_mean[p][c];

    float4 xv = *(const float4*)(x + rem);
    uint2 ou = *(const uint2*)(g_outT[p] + rem);
    float2 o01 = __bfloat1622float2(*reinterpret_cast<const __nv_bfloat162*>(&ou.x));
    float2 o23 = __bfloat1622float2(*reinterpret_cast<const __nv_bfloat162*>(&ou.y));

    float4 r;
    r.x = (xv.x + g*o01.x - mu) * wsc + bia;
    r.y = (xv.y + g*o01.y - mu) * wsc + bia;
    r.z = (xv.z + g*o23.x - mu) * wsc + bia;
    r.w = (xv.w + g*o23.y - mu) * wsc + bia;
    *(float4*)(out + e) = r;
}

// ---------------------------------------------------------------------------
// Launch
// ---------------------------------------------------------------------------
extern "C" void kernel_launch(void* const* d_in, const int* in_sizes, int n_in,
                              void* d_out, int out_size)
{
    const float* xr   = (const float*)d_in[0];
    const float* xi   = (const float*)d_in[1];
    const float* q_wr = (const float*)d_in[2];
    const float* q_wi = (const float*)d_in[3];
    const float* q_br = (const float*)d_in[4];
    const float* q_bi = (const float*)d_in[5];
    const float* k_wr = (const float*)d_in[6];
    const float* k_wi = (const float*)d_in[7];
    const float* k_br = (const float*)d_in[8];
    const float* k_bi = (const float*)d_in[9];
    const float* v_wr = (const float*)d_in[10];
    const float* v_wi = (const float*)d_in[11];
    const float* v_br = (const float*)d_in[12];
    const float* v_bi = (const float*)d_in[13];
    const float* gamma= (const float*)d_in[14];
    const float* bnwr = (const float*)d_in[15];
    const float* bnbr = (const float*)d_in[16];
    const float* bnwi = (const float*)d_in[17];
    const float* bnbi = (const float*)d_in[18];
    float* out = (float*)d_out;

    cudaFuncSetAttribute(k_scores, cudaFuncAttributeMaxDynamicSharedMemorySize, SC_SMEM);
    cudaFuncSetAttribute(k_av,     cudaFuncAttributeMaxDynamicSharedMemorySize, AV_SMEM);

    k_proj<0><<<dim3(Mtot/128, Cc/64), 256>>>(xr, xi, q_wr, q_wi, q_br, q_bi);
    k_proj<1><<<dim3(Mtot/128, Cc/64), 256>>>(xr, xi, k_wr, k_wi, k_br, k_bi);
    k_proj<2><<<dim3(Mtot/128, Cc/64), 256>>>(xr, xi, v_wr, v_wi, v_br, v_bi);

    k_scores<<<dim3(Nn/128, Nn/128, Bb), 256, SC_SMEM>>>();
    k_rowsum<<<Mtot/256, 256>>>();
    k_av<<<dim3(Nn/128, Cc/64, Bb), 256, AV_SMEM>>>();

    k_bnstats<<<dim3(Cc, 2), 256>>>(xr, xi, gamma);
    k_bnapply<<<(2*(size_t)Bb*Cc*Nn/4)/256, 256>>>(xr, xi, gamma, bnwr, bnbr, bnwi, bnbi, out);
}

// round 9
// speedup vs baseline: 1.1761x; 1.0763x over previous
#include <cuda_runtime.h>
#include <cuda_bf16.h>
#include <math.h>
#include <stdint.h>

#define Bb   8
#define Cc   256
#define Nn   2304
#define Mtot (Bb*Nn)
#define NMB  (Nn/128)      // 18 m-blocks per row
#define EPSf 1e-5f

// ---------------------------------------------------------------------------
// Scratch
// ---------------------------------------------------------------------------
__device__ __align__(128) __nv_bfloat16 g_q[2][(size_t)Mtot*Cc];
__device__ __align__(128) __nv_bfloat16 g_k[2][(size_t)Mtot*Cc];
__device__ __align__(128) __nv_bfloat16 g_v[2][(size_t)Mtot*Cc];
__device__ __align__(128) __nv_bfloat16 g_attnb[(size_t)Bb*Nn*Nn];   // bf16 exp(S) (unnormalized)
__device__ __align__(128) float g_psum[(size_t)Bb*NMB*Nn];           // partial row sums
__device__ __align__(128) float g_rinv[(size_t)Mtot];                // 1/rowsum
__device__ __align__(128) __nv_bfloat16 g_outT[2][(size_t)Bb*Cc*Nn]; // bf16 [p][b][c][n]
__device__ float g_mean[2][Cc];
__device__ float g_rstd[2][Cc];

// ---------------------------------------------------------------------------
// helpers
// ---------------------------------------------------------------------------
__device__ __forceinline__ uint32_t s2u(const void* p){
    return (uint32_t)__cvta_generic_to_shared(p);
}
__device__ __forceinline__ uint32_t packbf(float lo, float hi){
    uint32_t r;
    asm("cvt.rn.bf16x2.f32 %0, %1, %2;" : "=r"(r) : "f"(hi), "f"(lo));
    return r;
}
__device__ __forceinline__ void mma16(float* d, const uint32_t* a, const uint32_t* b){
    asm volatile("mma.sync.aligned.m16n8k16.row.col.f32.bf16.bf16.f32 "
        "{%0,%1,%2,%3}, {%4,%5,%6,%7}, {%8,%9}, {%0,%1,%2,%3};"
        : "+f"(d[0]),"+f"(d[1]),"+f"(d[2]),"+f"(d[3])
        : "r"(a[0]),"r"(a[1]),"r"(a[2]),"r"(a[3]),"r"(b[0]),"r"(b[1]));
}
__device__ __forceinline__ void ldsm4(uint32_t* r, uint32_t addr){
    asm volatile("ldmatrix.sync.aligned.m8n8.x4.shared.b16 {%0,%1,%2,%3}, [%4];"
        : "=r"(r[0]),"=r"(r[1]),"=r"(r[2]),"=r"(r[3]) : "r"(addr));
}
__device__ __forceinline__ void ldsm4t(uint32_t* r, uint32_t addr){
    asm volatile("ldmatrix.sync.aligned.m8n8.x4.trans.shared.b16 {%0,%1,%2,%3}, [%4];"
        : "=r"(r[0]),"=r"(r[1]),"=r"(r[2]),"=r"(r[3]) : "r"(addr));
}
__device__ __forceinline__ void cpa16(uint32_t dst, const void* src){
    asm volatile("cp.async.cg.shared.global [%0], [%1], 16;" :: "r"(dst), "l"(src));
}
#define CP_COMMIT() asm volatile("cp.async.commit_group;")
#define CP_WAIT(N)  asm volatile("cp.async.wait_group %0;" :: "n"(N))

// 64B-row smem tile: swizzled 16B-chunk offset
__device__ __forceinline__ uint32_t sw64(uint32_t tile, int r, int c16){
    return tile + (uint32_t)r*64u + (uint32_t)((c16 ^ ((r>>1)&3))<<4);
}
// 128B-row smem tile: swizzled 16B-chunk offset (8 chunks/row)
__device__ __forceinline__ uint32_t sw128(uint32_t tile, int r, int c16){
    return tile + (uint32_t)r*128u + (uint32_t)((c16 ^ (r&7))<<4);
}

// ---------------------------------------------------------------------------
// Kernel 1: complex projection (mma.sync bf16), fp32 in, bf16 out [m][c]
//   Single launch: blockIdx.z selects Q/K/V.
// ---------------------------------------------------------------------------
__global__ void __launch_bounds__(256) k_proj(
    const float* __restrict__ xr, const float* __restrict__ xi,
    const float* __restrict__ qwr, const float* __restrict__ qwi,
    const float* __restrict__ qbr, const float* __restrict__ qbi,
    const float* __restrict__ kwr, const float* __restrict__ kwi,
    const float* __restrict__ kbr, const float* __restrict__ kbi,
    const float* __restrict__ vwr, const float* __restrict__ vwi,
    const float* __restrict__ vbr, const float* __restrict__ vbi)
{
    const int wsel = blockIdx.z;
    const float* wr  = (wsel==0)?qwr:(wsel==1)?kwr:vwr;
    const float* wi  = (wsel==0)?qwi:(wsel==1)?kwi:vwi;
    const float* brv = (wsel==0)?qbr:(wsel==1)?kbr:vbr;
    const float* biv = (wsel==0)?qbi:(wsel==1)?kbi:vbi;
    __nv_bfloat16* yr = (wsel==0)?g_q[0]:(wsel==1)?g_k[0]:g_v[0];
    __nv_bfloat16* yi = (wsel==0)?g_q[1]:(wsel==1)?g_k[1]:g_v[1];

    __shared__ __nv_bfloat16 sX[2][16][136];   // [part][k][m]
    __shared__ __nv_bfloat16 sW[2][64][24];    // [part][d][k]

    const int tid = threadIdx.x;
    const int w = tid >> 5, lane = tid & 31;
    const int gr = lane >> 2, tg = lane & 3;
    const int wm = w & 3, wn = w >> 2;
    const int m0 = blockIdx.x * 128;
    const int d0 = blockIdx.y * 64;
    const int b  = m0 / Nn;
    const int n0 = m0 - b*Nn;

    const int lp = tid >> 7;
    const int lt = tid & 127;

    float accr[2][4][4], acci[2][4][4];
    #pragma unroll
    for (int mf=0; mf<2; ++mf)
        #pragma unroll
        for (int nf=0; nf<4; ++nf)
            #pragma unroll
            for (int e=0; e<4; ++e){ accr[mf][nf][e]=0.f; acci[mf][nf][e]=0.f; }

    for (int kt = 0; kt < Cc/16; ++kt) {
        const int ck = kt*16;
        const float* xs = lp ? xi : xr;
        const float* ws = lp ? wi : wr;
        #pragma unroll
        for (int it=0; it<4; ++it) {
            int idx = lt + 128*it;
            int c = idx >> 5, nq = idx & 31;
            const float4 v = *(const float4*)(xs + (size_t)b*Cc*Nn + (size_t)(ck+c)*Nn + n0 + nq*4);
            uint2 pk = make_uint2(packbf(v.x,v.y), packbf(v.z,v.w));
            *(uint2*)&sX[lp][c][nq*4] = pk;
        }
        #pragma unroll
        for (int it=0; it<2; ++it) {
            int idx = lt + 128*it;
            int d = idx >> 2, cq = idx & 3;
            const float4 v = *(const float4*)(ws + (size_t)(d0+d)*Cc + ck + cq*4);
            uint2 pk = make_uint2(packbf(v.x,v.y), packbf(v.z,v.w));
            *(uint2*)&sW[lp][d][cq*4] = pk;
        }
        __syncthreads();

        uint32_t axr[2][4], axi[2][4], ain[2][4];
        #pragma unroll
        for (int mf=0; mf<2; ++mf) {
            int rb = wm*32 + mf*16;
            ldsm4t(axr[mf], s2u(&sX[0][(lane&7) + (lane>>4)*8][rb + ((lane>>3)&1)*8]));
            ldsm4t(axi[mf], s2u(&sX[1][(lane&7) + (lane>>4)*8][rb + ((lane>>3)&1)*8]));
            #pragma unroll
            for (int e=0;e<4;++e) ain[mf][e] = axi[mf][e] ^ 0x80008000u;
        }
        #pragma unroll
        for (int nf2=0; nf2<2; ++nf2) {
            int cb = wn*32 + nf2*16;
            uint32_t bwr[4], bwi[4];
            ldsm4(bwr, s2u(&sW[0][cb + (lane>>4)*8 + (lane&7)][((lane>>3)&1)*8]));
            ldsm4(bwi, s2u(&sW[1][cb + (lane>>4)*8 + (lane&7)][((lane>>3)&1)*8]));
            #pragma unroll
            for (int h=0; h<2; ++h) {
                int nfr = nf2*2 + h;
                #pragma unroll
                for (int mf=0; mf<2; ++mf) {
                    mma16(accr[mf][nfr], axr[mf], bwr + 2*h);
                    mma16(accr[mf][nfr], ain[mf], bwi + 2*h);
                    mma16(acci[mf][nfr], axr[mf], bwi + 2*h);
                    mma16(acci[mf][nfr], axi[mf], bwr + 2*h);
                }
            }
        }
        __syncthreads();
    }

    #pragma unroll
    for (int mf=0; mf<2; ++mf) {
        const int row0 = m0 + wm*32 + mf*16 + gr;
        #pragma unroll
        for (int nfr=0; nfr<4; ++nfr) {
            const int col0 = d0 + wn*32 + nfr*8 + 2*tg;
            const float b0r = brv[col0], b1r = brv[col0+1];
            const float b0i = biv[col0], b1i = biv[col0+1];
            *(uint32_t*)&yr[(size_t)row0*Cc + col0]     = packbf(accr[mf][nfr][0]+b0r, accr[mf][nfr][1]+b1r);
            *(uint32_t*)&yr[(size_t)(row0+8)*Cc + col0] = packbf(accr[mf][nfr][2]+b0r, accr[mf][nfr][3]+b1r);
            *(uint32_t*)&yi[(size_t)row0*Cc + col0]     = packbf(acci[mf][nfr][0]+b0i, acci[mf][nfr][1]+b1i);
            *(uint32_t*)&yi[(size_t)(row0+8)*Cc + col0] = packbf(acci[mf][nfr][2]+b0i, acci[mf][nfr][3]+b1i);
        }
    }
}

// ---------------------------------------------------------------------------
// Kernel 2: scores + exp. Block 128n x 128m, warps 2(n)x4(m), warp 64x32.
//   3-stage ring, K-step 32. Epilogue: exp(s/16) -> bf16 g_attnb +
//   deterministic per-block partial row sums -> g_psum.
// ---------------------------------------------------------------------------
#define SC_STAGE 32768
#define SC_SMEM  (3*SC_STAGE)

__global__ void __launch_bounds__(256) k_scores()
{
    extern __shared__ __align__(16) unsigned char dyn[];
    const uint32_t base = s2u(dyn);

    const int tid = threadIdx.x;
    const int w = tid >> 5, lane = tid & 31;
    const int gr = lane >> 2, tg = lane & 3;
    const int wrow = w & 1, wcol = w >> 1;
    const int m0 = blockIdx.x * 128;
    const int n0 = blockIdx.y * 128;
    const int b  = blockIdx.z;

    const __nv_bfloat16* srcs[4] = {
        g_q[0] + (size_t)b*Nn*Cc, g_q[1] + (size_t)b*Nn*Cc,
        g_k[0] + (size_t)b*Nn*Cc, g_k[1] + (size_t)b*Nn*Cc };
    const int rbase[4] = { n0, n0, m0, m0 };

    float acc[4][4][4];
    #pragma unroll
    for (int mf=0; mf<4; ++mf)
        #pragma unroll
        for (int nf=0; nf<4; ++nf)
            #pragma unroll
            for (int e=0; e<4; ++e) acc[mf][nf][e]=0.f;

    auto load_stage = [&](int s, int ck){
        const uint32_t st = base + s*SC_STAGE;
        #pragma unroll
        for (int t=0;t<4;++t){
            const uint32_t tb = st + t*8192;
            #pragma unroll
            for (int it=0; it<2; ++it){
                int idx = tid + 256*it;
                int r = idx>>2, c = idx&3;
                cpa16(sw64(tb, r, c), srcs[t] + (size_t)(rbase[t]+r)*Cc + ck + c*8);
            }
        }
        CP_COMMIT();
    };

    load_stage(0, 0);
    load_stage(1, 32);

    for (int kt = 0; kt < 8; ++kt) {
        const int s = kt % 3;
        if (kt < 7) { CP_WAIT(1); } else { CP_WAIT(0); }
        __syncthreads();
        if (kt + 2 < 8) load_stage((kt+2)%3, (kt+2)*32);

        const uint32_t st = base + s*SC_STAGE;
        #pragma unroll
        for (int p=0; p<2; ++p) {
            const uint32_t qt = st + p*8192;
            const uint32_t ktile = st + 16384 + p*8192;
            #pragma unroll
            for (int ks=0; ks<32; ks+=16) {
                uint32_t a[4][4];
                #pragma unroll
                for (int mf=0; mf<4; ++mf) {
                    int r = wrow*64 + mf*16 + (lane&15);
                    int c16 = (ks>>3) + (lane>>4);
                    ldsm4(a[mf], sw64(qt, r, c16));
                }
                #pragma unroll
                for (int nf2=0; nf2<2; ++nf2) {
                    int rr = wcol*32 + nf2*16 + (lane>>4)*8 + (lane&7);
                    int c16 = (ks>>3) + ((lane>>3)&1);
                    uint32_t bb[4];
                    ldsm4(bb, sw64(ktile, rr, c16));
                    #pragma unroll
                    for (int mf=0; mf<4; ++mf) {
                        mma16(acc[mf][nf2*2  ], a[mf], bb);
                        mma16(acc[mf][nf2*2+1], a[mf], bb+2);
                    }
                }
            }
        }
        __syncthreads();
    }

    // epilogue: exp + store + deterministic partial row sums
    float (*spsum)[128] = (float(*)[128])dyn;   // [wcol][row_local], 2KB
    const float sc = 1.0f/16.0f;
    #pragma unroll
    for (int mf=0; mf<4; ++mf) {
        const int row0 = n0 + wrow*64 + mf*16 + gr;
        const size_t r0b = (size_t)b*Nn*Nn + (size_t)row0*Nn;
        const size_t r1b = r0b + (size_t)8*Nn;
        float p0 = 0.f, p1 = 0.f;
        #pragma unroll
        for (int nfr=0; nfr<4; ++nfr) {
            const int col0 = m0 + wcol*32 + nfr*8 + 2*tg;
            float e0 = __expf(acc[mf][nfr][0]*sc);
            float e1 = __expf(acc[mf][nfr][1]*sc);
            float e2 = __expf(acc[mf][nfr][2]*sc);
            float e3 = __expf(acc[mf][nfr][3]*sc);
            *(uint32_t*)&g_attnb[r0b + col0] = packbf(e0, e1);
            *(uint32_t*)&g_attnb[r1b + col0] = packbf(e2, e3);
            p0 += e0 + e1;
            p1 += e2 + e3;
        }
        p0 += __shfl_xor_sync(0xFFFFFFFFu, p0, 1);
        p0 += __shfl_xor_sync(0xFFFFFFFFu, p0, 2);
        p1 += __shfl_xor_sync(0xFFFFFFFFu, p1, 1);
        p1 += __shfl_xor_sync(0xFFFFFFFFu, p1, 2);
        if (tg == 0) {
            spsum[wcol][wrow*64 + mf*16 + gr    ] = p0;
            spsum[wcol][wrow*64 + mf*16 + gr + 8] = p1;
        }
    }
    __syncthreads();
    if (tid < 128) {
        float s4 = spsum[0][tid] + spsum[1][tid] + spsum[2][tid] + spsum[3][tid];
        g_psum[((size_t)b*NMB + (m0>>7))*Nn + n0 + tid] = s4;
    }
}

// ---------------------------------------------------------------------------
// Kernel 3: row-sum reduce -> 1/sum
// ---------------------------------------------------------------------------
__global__ void __launch_bounds__(256) k_rowsum()
{
    const int i = blockIdx.x*256 + threadIdx.x;   // b*Nn + n
    const int b = i / Nn, n = i - b*Nn;
    float s = 0.f;
    #pragma unroll
    for (int mb=0; mb<NMB; ++mb)
        s += g_psum[((size_t)b*NMB + mb)*Nn + n];
    g_rinv[i] = 1.f / s;
}

// ---------------------------------------------------------------------------
// Kernel 4: AV. Block 128n x 64d, warps 4(n)x2(d). 3-stage ring, K-step 64.
//   Stage: A 128 rows x 128B (sw128, 16KB) + V 2 parts x 64 rows x 144B (18KB).
//   A = unnormalized exp; epilogue scales by g_rinv[n]. Output bf16 [d][n].
// ---------------------------------------------------------------------------
#define AV_VOFF  16384
#define AV_STAGE (16384 + 18432)   // 34816
#define AV_SMEM  (3*AV_STAGE)      // 104448

__global__ void __launch_bounds__(256) k_av()
{
    extern __shared__ __align__(16) unsigned char dyn[];
    const uint32_t base = s2u(dyn);

    const int tid = threadIdx.x;
    const int w = tid >> 5, lane = tid & 31;
    const int gr = lane >> 2, tg = lane & 3;
    const int wm = w & 3, wn = w >> 2;
    const int n0 = blockIdx.x * 128;
    const int d0 = blockIdx.y * 64;
    const int b  = blockIdx.z;

    const __nv_bfloat16* Ab  = g_attnb + (size_t)b*Nn*Nn;
    const __nv_bfloat16* vp[2] = { g_v[0] + (size_t)b*Nn*Cc, g_v[1] + (size_t)b*Nn*Cc };

    float accr[2][4][4], acci[2][4][4];
    #pragma unroll
    for (int mf=0; mf<2; ++mf)
        #pragma unroll
        for (int nf=0; nf<4; ++nf)
            #pragma unroll
            for (int e=0; e<4; ++e){ accr[mf][nf][e]=0.f; acci[mf][nf][e]=0.f; }

    auto load_stage = [&](int s, int mk){
        const uint32_t st = base + s*AV_STAGE;
        // A: 128 rows x 8 chunks (128B rows, sw128)
        #pragma unroll
        for (int it=0; it<4; ++it){
            int idx = tid + 256*it;
            int r = idx>>3, c = idx&7;
            cpa16(sw128(st, r, c), Ab + (size_t)(n0+r)*Nn + mk + c*8);
        }
        // V: 2 parts x 64 rows x 8 chunks, 144B row pitch
        #pragma unroll
        for (int it=0; it<4; ++it){
            int idx = tid + 256*it;
            int p = idx>>9, r = (idx>>3)&63, c = idx&7;
            cpa16(st + AV_VOFF + p*9216 + r*144 + c*16,
                  vp[p] + (size_t)(mk+r)*Cc + d0 + c*8);
        }
        CP_COMMIT();
    };

    load_stage(0, 0);
    load_stage(1, 64);

    const int NKT = Nn/64;   // 36
    for (int kt = 0; kt < NKT; ++kt) {
        const int s = kt % 3;
        if (kt < NKT-1) { CP_WAIT(1); } else { CP_WAIT(0); }
        __syncthreads();
        if (kt + 2 < NKT) load_stage((kt+2)%3, (kt+2)*64);

        const uint32_t st = base + s*AV_STAGE;
        #pragma unroll
        for (int ks=0; ks<64; ks+=16) {
            uint32_t a[2][4];
            #pragma unroll
            for (int mf=0; mf<2; ++mf) {
                int r = wm*32 + mf*16 + (lane&15);
                int c16 = (ks>>3) + (lane>>4);
                ldsm4(a[mf], sw128(st, r, c16));
            }
            #pragma unroll
            for (int nf2=0; nf2<2; ++nf2) {
                int cb = wn*32 + nf2*16;
                uint32_t bvr[4], bvi[4];
                uint32_t vaddr = st + AV_VOFF + (uint32_t)(ks + (lane&15))*144 + (uint32_t)(cb + (lane>>4)*8)*2;
                ldsm4t(bvr, vaddr);
                ldsm4t(bvi, vaddr + 9216);
                #pragma unroll
                for (int h=0; h<2; ++h) {
                    int nfr = nf2*2 + h;
                    #pragma unroll
                    for (int mf=0; mf<2; ++mf) {
                        mma16(accr[mf][nfr], a[mf], bvr + 2*h);
                        mma16(acci[mf][nfr], a[mf], bvi + 2*h);
                    }
                }
            }
        }
        __syncthreads();
    }

    // normalization factors for this thread's rows
    float rin[2][2];
    #pragma unroll
    for (int mf=0; mf<2; ++mf) {
        rin[mf][0] = g_rinv[(size_t)b*Nn + n0 + wm*32 + mf*16 + gr];
        rin[mf][1] = g_rinv[(size_t)b*Nn + n0 + wm*32 + mf*16 + gr + 8];
    }

    // transpose epilogue -> g_outT [d][n] bf16 (smem reuse)
    __nv_bfloat16 (*stage)[144] = (__nv_bfloat16(*)[144])dyn;
    const size_t basep = (size_t)b*Cc*Nn + (size_t)d0*Nn + n0;
    #pragma unroll
    for (int p=0; p<2; ++p) {
        __syncthreads();
        #pragma unroll
        for (int mf=0; mf<2; ++mf) {
            int rl = wm*32 + mf*16 + gr;
            #pragma unroll
            for (int nfr=0; nfr<4; ++nfr) {
                int cl = wn*32 + nfr*8 + 2*tg;
                float* acc = p ? acci[mf][nfr] : accr[mf][nfr];
                stage[cl  ][rl  ] = __float2bfloat16(acc[0]*rin[mf][0]);
                stage[cl+1][rl  ] = __float2bfloat16(acc[1]*rin[mf][0]);
                stage[cl  ][rl+8] = __float2bfloat16(acc[2]*rin[mf][1]);
                stage[cl+1][rl+8] = __float2bfloat16(acc[3]*rin[mf][1]);
            }
        }
        __syncthreads();
        #pragma unroll
        for (int it=0; it<4; ++it) {
            int idx = tid + 256*it;
            int dl = idx >> 4, c8 = idx & 15;
            *(uint4*)(g_outT[p] + basep + (size_t)dl*Nn + c8*8) = *(const uint4*)&stage[dl][c8*8];
        }
    }
}

// ---------------------------------------------------------------------------
// Kernel 5/6: BatchNorm (bf16 outT, vectorized)
// ---------------------------------------------------------------------------
__global__ void __launch_bounds__(256) k_bnstats(
    const float* __restrict__ xr, const float* __restrict__ xi,
    const float* __restrict__ gamma)
{
    const int c = blockIdx.x, p = blockIdx.y;
    const int tid = threadIdx.x;
    const float* x = p ? xi : xr;
    const __nv_bfloat16* o = g_outT[p];
    const float g = gamma[0];

    float s = 0.f, ss = 0.f;
    for (int b = 0; b < Bb; ++b) {
        const size_t bb = (size_t)b*Cc*Nn + (size_t)c*Nn;
        for (int n4 = tid; n4 < Nn/4; n4 += 256) {
            float4 xv = *(const float4*)(x + bb + n4*4);
            uint2 ou = *(const uint2*)(o + bb + n4*4);
            float2 o01 = __bfloat1622float2(*reinterpret_cast<const __nv_bfloat162*>(&ou.x));
            float2 o23 = __bfloat1622float2(*reinterpret_cast<const __nv_bfloat162*>(&ou.y));
            float z0 = xv.x + g*o01.x, z1 = xv.y + g*o01.y;
            float z2 = xv.z + g*o23.x, z3 = xv.w + g*o23.y;
            s  += z0+z1+z2+z3;
            ss += z0*z0+z1*z1+z2*z2+z3*z3;
        }
    }
    __shared__ float rs[256], rss[256];
    rs[tid] = s; rss[tid] = ss; __syncthreads();
    #pragma unroll
    for (int st = 128; st > 0; st >>= 1) {
        if (tid < st) { rs[tid] += rs[tid+st]; rss[tid] += rss[tid+st]; }
        __syncthreads();
    }
    if (tid == 0) {
        const float inv_cnt = 1.f / (float)Mtot;
        float mean = rs[0] * inv_cnt;
        float var  = rss[0] * inv_cnt - mean*mean;
        g_mean[p][c] = mean;
        g_rstd[p][c] = rsqrtf(var + EPSf);
    }
}

__global__ void __launch_bounds__(256) k_bnapply(
    const float* __restrict__ xr, const float* __restrict__ xi,
    const float* __restrict__ gamma,
    const float* __restrict__ bnwr, const float* __restrict__ bnbr,
    const float* __restrict__ bnwi, const float* __restrict__ bnbi,
    float* __restrict__ out)
{
    const int idx4 = blockIdx.x*256 + threadIdx.x;
    const size_t e = (size_t)idx4 * 4;
    const size_t half = (size_t)Bb*Cc*Nn;
    const int p = (e >= half) ? 1 : 0;
    const size_t rem = e - (size_t)p*half;
    const int c = (int)((rem / Nn) % Cc);

    const float* x = p ? xi : xr;
    const float g = gamma[0];
    const float wsc = (p ? bnwi[c] : bnwr[c]) * g_rstd[p][c];
    const float bia = (p ? bnbi[c] : bnbr[c]);
    const float mu = g_mean[p][c];

    float4 xv = *(const float4*)(x + rem);
    uint2 ou = *(const uint2*)(g_outT[p] + rem);
    float2 o01 = __bfloat1622float2(*reinterpret_cast<const __nv_bfloat162*>(&ou.x));
    float2 o23 = __bfloat1622float2(*reinterpret_cast<const __nv_bfloat162*>(&ou.y));

    float4 r;
    r.x = (xv.x + g*o01.x - mu) * wsc + bia;
    r.y = (xv.y + g*o01.y - mu) * wsc + bia;
    r.z = (xv.z + g*o23.x - mu) * wsc + bia;
    r.w = (xv.w + g*o23.y - mu) * wsc + bia;
    *(float4*)(out + e) = r;
}

// ---------------------------------------------------------------------------
// Launch
// ---------------------------------------------------------------------------
extern "C" void kernel_launch(void* const* d_in, const int* in_sizes, int n_in,
                              void* d_out, int out_size)
{
    const float* xr   = (const float*)d_in[0];
    const float* xi   = (const float*)d_in[1];
    const float* q_wr = (const float*)d_in[2];
    const float* q_wi = (const float*)d_in[3];
    const float* q_br = (const float*)d_in[4];
    const float* q_bi = (const float*)d_in[5];
    const float* k_wr = (const float*)d_in[6];
    const float* k_wi = (const float*)d_in[7];
    const float* k_br = (const float*)d_in[8];
    const float* k_bi = (const float*)d_in[9];
    const float* v_wr = (const float*)d_in[10];
    const float* v_wi = (const float*)d_in[11];
    const float* v_br = (const float*)d_in[12];
    const float* v_bi = (const float*)d_in[13];
    const float* gamma= (const float*)d_in[14];
    const float* bnwr = (const float*)d_in[15];
    const float* bnbr = (const float*)d_in[16];
    const float* bnwi = (const float*)d_in[17];
    const float* bnbi = (const float*)d_in[18];
    float* out = (float*)d_out;

    cudaFuncSetAttribute(k_scores, cudaFuncAttributeMaxDynamicSharedMemorySize, SC_SMEM);
    cudaFuncSetAttribute(k_av,     cudaFuncAttributeMaxDynamicSharedMemorySize, AV_SMEM);

    k_proj<<<dim3(Mtot/128, Cc/64, 3), 256>>>(xr, xi,
        q_wr, q_wi, q_br, q_bi, k_wr, k_wi, k_br, k_bi, v_wr, v_wi, v_br, v_bi);

    k_scores<<<dim3(Nn/128, Nn/128, Bb), 256, SC_SMEM>>>();
    k_rowsum<<<Mtot/256, 256>>>();
    k_av<<<dim3(Nn/128, Cc/64, Bb), 256, AV_SMEM>>>();

    k_bnstats<<<dim3(Cc, 2), 256>>>(xr, xi, gamma);
    k_bnapply<<<(2*(size_t)Bb*Cc*Nn/4)/256, 256>>>(xr, xi, gamma, bnwr, bnbr, bnwi, bnbi, out);
}

// round 11
// speedup vs baseline: 1.2658x; 1.0762x over previous
#include <cuda_runtime.h>
#include <cuda_bf16.h>
#include <math.h>
#include <stdint.h>

#define Bb   8
#define Cc   256
#define Nn   2304
#define Mtot (Bb*Nn)
#define NMB  (Nn/128)      // 18 m-blocks per row
#define EPSf 1e-5f

// ---------------------------------------------------------------------------
// Scratch
// ---------------------------------------------------------------------------
__device__ __align__(128) __nv_bfloat16 g_xb[2][(size_t)Bb*Cc*Nn];   // bf16 X [p][b][c][n]
__device__ __align__(128) __nv_bfloat16 g_wb[6][(size_t)Cc*Cc];      // bf16 W [qr,qi,kr,ki,vr,vi][d][c]
__device__ __align__(128) __nv_bfloat16 g_q[2][(size_t)Mtot*Cc];
__device__ __align__(128) __nv_bfloat16 g_k[2][(size_t)Mtot*Cc];
__device__ __align__(128) __nv_bfloat16 g_v[2][(size_t)Mtot*Cc];
__device__ __align__(128) __nv_bfloat16 g_attnb[(size_t)Bb*Nn*Nn];   // bf16 exp(S) (unnormalized)
__device__ __align__(128) float g_psum[(size_t)Bb*NMB*Nn];           // partial row sums
__device__ __align__(128) float g_rinv[(size_t)Mtot];                // 1/rowsum
__device__ __align__(128) __nv_bfloat16 g_outT[2][(size_t)Bb*Cc*Nn]; // bf16 [p][b][c][n]
__device__ float g_mean[2][Cc];
__device__ float g_rstd[2][Cc];

// ---------------------------------------------------------------------------
// helpers
// ---------------------------------------------------------------------------
__device__ __forceinline__ uint32_t s2u(const void* p){
    return (uint32_t)__cvta_generic_to_shared(p);
}
__device__ __forceinline__ uint32_t packbf(float lo, float hi){
    uint32_t r;
    asm("cvt.rn.bf16x2.f32 %0, %1, %2;" : "=r"(r) : "f"(hi), "f"(lo));
    return r;
}
__device__ __forceinline__ void mma16(float* d, const uint32_t* a, const uint32_t* b){
    asm volatile("mma.sync.aligned.m16n8k16.row.col.f32.bf16.bf16.f32 "
        "{%0,%1,%2,%3}, {%4,%5,%6,%7}, {%8,%9}, {%0,%1,%2,%3};"
        : "+f"(d[0]),"+f"(d[1]),"+f"(d[2]),"+f"(d[3])
        : "r"(a[0]),"r"(a[1]),"r"(a[2]),"r"(a[3]),"r"(b[0]),"r"(b[1]));
}
__device__ __forceinline__ void ldsm4(uint32_t* r, uint32_t addr){
    asm volatile("ldmatrix.sync.aligned.m8n8.x4.shared.b16 {%0,%1,%2,%3}, [%4];"
        : "=r"(r[0]),"=r"(r[1]),"=r"(r[2]),"=r"(r[3]) : "r"(addr));
}
__device__ __forceinline__ void ldsm4t(uint32_t* r, uint32_t addr){
    asm volatile("ldmatrix.sync.aligned.m8n8.x4.trans.shared.b16 {%0,%1,%2,%3}, [%4];"
        : "=r"(r[0]),"=r"(r[1]),"=r"(r[2]),"=r"(r[3]) : "r"(addr));
}
__device__ __forceinline__ void cpa16(uint32_t dst, const void* src){
    asm volatile("cp.async.cg.shared.global [%0], [%1], 16;" :: "r"(dst), "l"(src));
}
#define CP_COMMIT() asm volatile("cp.async.commit_group;")
#define CP_WAIT(N)  asm volatile("cp.async.wait_group %0;" :: "n"(N))

// 64B-row smem tile: swizzled 16B-chunk offset
__device__ __forceinline__ uint32_t sw64(uint32_t tile, int r, int c16){
    return tile + (uint32_t)r*64u + (uint32_t)((c16 ^ ((r>>1)&3))<<4);
}
// 128B-row smem tile: swizzled 16B-chunk offset (8 chunks/row)
__device__ __forceinline__ uint32_t sw128(uint32_t tile, int r, int c16){
    return tile + (uint32_t)r*128u + (uint32_t)((c16 ^ (r&7))<<4);
}

// ---------------------------------------------------------------------------
// Kernel 0a: convert X fp32 -> bf16 (both parts)
// ---------------------------------------------------------------------------
__global__ void __launch_bounds__(256) k_cvt(
    const float* __restrict__ xr, const float* __restrict__ xi)
{
    const size_t i8 = ((size_t)blockIdx.x*256 + threadIdx.x) * 8;
    const size_t half = (size_t)Bb*Cc*Nn;
    const int p = (i8 >= half) ? 1 : 0;
    const size_t rem = i8 - (size_t)p*half;
    const float* x = p ? xi : xr;
    float4 a = *(const float4*)(x + rem);
    float4 b = *(const float4*)(x + rem + 4);
    uint4 o;
    o.x = packbf(a.x,a.y); o.y = packbf(a.z,a.w);
    o.z = packbf(b.x,b.y); o.w = packbf(b.z,b.w);
    *(uint4*)(g_xb[p] + rem) = o;
}

// ---------------------------------------------------------------------------
// Kernel 0b: convert the 6 weight matrices fp32 -> bf16
// ---------------------------------------------------------------------------
__global__ void __launch_bounds__(256) k_cvtw(
    const float* __restrict__ qwr, const float* __restrict__ qwi,
    const float* __restrict__ kwr, const float* __restrict__ kwi,
    const float* __restrict__ vwr, const float* __restrict__ vwi)
{
    const float* mats[6] = { qwr, qwi, kwr, kwi, vwr, vwi };
    const int i8 = (blockIdx.x*256 + threadIdx.x) * 8;   // 6*65536 total
    const int mat = i8 >> 16;
    const int rem = i8 & 65535;
    const float* src = mats[mat];
    float4 a = *(const float4*)(src + rem);
    float4 b = *(const float4*)(src + rem + 4);
    uint4 o;
    o.x = packbf(a.x,a.y); o.y = packbf(a.z,a.w);
    o.z = packbf(b.x,b.y); o.w = packbf(b.z,b.w);
    *(uint4*)(g_wb[mat] + rem) = o;
}

// ---------------------------------------------------------------------------
// Kernel 1: complex projection, cp.async 3-stage ring, K-step 32.
//   Block 128m x 64d, warps 4(m)x2(d), warp tile 32x32. blockIdx.z = Q/K/V.
//   Stage: X 2 parts x [32 c][136 m pitch] (17408B) + W 2 parts x sw64 64x64B
//   (8192B) = 25600B.
// ---------------------------------------------------------------------------
#define PJ_XPART 8704
#define PJ_WOFF  17408
#define PJ_WPART 4096
#define PJ_STAGE 25600
#define PJ_SMEM  (3*PJ_STAGE)

__global__ void __launch_bounds__(256) k_proj(
    const float* __restrict__ qbr, const float* __restrict__ qbi,
    const float* __restrict__ kbr, const float* __restrict__ kbi,
    const float* __restrict__ vbr, const float* __restrict__ vbi)
{
    extern __shared__ __align__(16) unsigned char dyn[];
    const uint32_t base = s2u(dyn);

    const int wsel = blockIdx.z;
    const float* brv = (wsel==0)?qbr:(wsel==1)?kbr:vbr;
    const float* biv = (wsel==0)?qbi:(wsel==1)?kbi:vbi;
    __nv_bfloat16* yr = (wsel==0)?g_q[0]:(wsel==1)?g_k[0]:g_v[0];
    __nv_bfloat16* yi = (wsel==0)?g_q[1]:(wsel==1)?g_k[1]:g_v[1];

    const int tid = threadIdx.x;
    const int w = tid >> 5, lane = tid & 31;
    const int gr = lane >> 2, tg = lane & 3;
    const int wm = w & 3, wn = w >> 2;
    const int m0 = blockIdx.x * 128;
    const int d0 = blockIdx.y * 64;
    const int b  = m0 / Nn;
    const int n0 = m0 - b*Nn;

    const __nv_bfloat16* xbp[2] = { g_xb[0] + (size_t)b*Cc*Nn, g_xb[1] + (size_t)b*Cc*Nn };
    const __nv_bfloat16* wbp[2] = { g_wb[wsel*2], g_wb[wsel*2+1] };

    float accr[2][4][4], acci[2][4][4];
    #pragma unroll
    for (int mf=0; mf<2; ++mf)
        #pragma unroll
        for (int nf=0; nf<4; ++nf)
            #pragma unroll
            for (int e=0; e<4; ++e){ accr[mf][nf][e]=0.f; acci[mf][nf][e]=0.f; }

    auto load_stage = [&](int s, int ck){
        const uint32_t st = base + s*PJ_STAGE;
        // X: 2 parts x 32 c-rows x 16 chunks (pitch 272B)
        #pragma unroll
        for (int it=0; it<4; ++it){
            int idx = tid + 256*it;
            int p = idx>>9, r = (idx>>4)&31, c = idx&15;
            cpa16(st + p*PJ_XPART + r*272 + c*16,
                  xbp[p] + (size_t)(ck+r)*Nn + n0 + c*8);
        }
        // W: 2 parts x 64 d-rows x 4 chunks (sw64)
        #pragma unroll
        for (int it=0; it<2; ++it){
            int idx = tid + 256*it;
            int p = idx>>8, r = (idx>>2)&63, c = idx&3;
            cpa16(sw64(st + PJ_WOFF + p*PJ_WPART, r, c),
                  wbp[p] + (size_t)(d0+r)*Cc + ck + c*8);
        }
        CP_COMMIT();
    };

    load_stage(0, 0);
    load_stage(1, 32);

    for (int kt = 0; kt < 8; ++kt) {
        const int s = kt % 3;
        if (kt < 7) { CP_WAIT(1); } else { CP_WAIT(0); }
        __syncthreads();
        if (kt + 2 < 8) load_stage((kt+2)%3, (kt+2)*32);

        const uint32_t st = base + s*PJ_STAGE;
        #pragma unroll
        for (int ks=0; ks<32; ks+=16) {
            uint32_t axr[2][4], axi[2][4], ain[2][4];
            #pragma unroll
            for (int mf=0; mf<2; ++mf) {
                int crow = ks + (lane&7) + (lane>>4)*8;
                int mcol = wm*32 + mf*16 + ((lane>>3)&1)*8;
                ldsm4t(axr[mf], st + 0*PJ_XPART + (uint32_t)crow*272 + (uint32_t)mcol*2);
                ldsm4t(axi[mf], st + 1*PJ_XPART + (uint32_t)crow*272 + (uint32_t)mcol*2);
                #pragma unroll
                for (int e=0;e<4;++e) ain[mf][e] = axi[mf][e] ^ 0x80008000u;
            }
            #pragma unroll
            for (int nf2=0; nf2<2; ++nf2) {
                int rr = wn*32 + nf2*16 + (lane>>4)*8 + (lane&7);
                int c16 = (ks>>3) + ((lane>>3)&1);
                uint32_t bwr[4], bwi[4];
                ldsm4(bwr, sw64(st + PJ_WOFF,            rr, c16));
                ldsm4(bwi, sw64(st + PJ_WOFF + PJ_WPART, rr, c16));
                #pragma unroll
                for (int h=0; h<2; ++h) {
                    int nfr = nf2*2 + h;
                    #pragma unroll
                    for (int mf=0; mf<2; ++mf) {
                        mma16(accr[mf][nfr], axr[mf], bwr + 2*h);
                        mma16(accr[mf][nfr], ain[mf], bwi + 2*h);
                        mma16(acci[mf][nfr], axr[mf], bwi + 2*h);
                        mma16(acci[mf][nfr], axi[mf], bwr + 2*h);
                    }
                }
            }
        }
        __syncthreads();
    }

    #pragma unroll
    for (int mf=0; mf<2; ++mf) {
        const int row0 = m0 + wm*32 + mf*16 + gr;
        #pragma unroll
        for (int nfr=0; nfr<4; ++nfr) {
            const int col0 = d0 + wn*32 + nfr*8 + 2*tg;
            const float b0r = brv[col0], b1r = brv[col0+1];
            const float b0i = biv[col0], b1i = biv[col0+1];
            *(uint32_t*)&yr[(size_t)row0*Cc + col0]     = packbf(accr[mf][nfr][0]+b0r, accr[mf][nfr][1]+b1r);
            *(uint32_t*)&yr[(size_t)(row0+8)*Cc + col0] = packbf(accr[mf][nfr][2]+b0r, accr[mf][nfr][3]+b1r);
            *(uint32_t*)&yi[(size_t)row0*Cc + col0]     = packbf(acci[mf][nfr][0]+b0i, acci[mf][nfr][1]+b1i);
            *(uint32_t*)&yi[(size_t)(row0+8)*Cc + col0] = packbf(acci[mf][nfr][2]+b0i, acci[mf][nfr][3]+b1i);
        }
    }
}

// ---------------------------------------------------------------------------
// Kernel 2: scores + exp. Block 128n x 128m, warps 2(n)x4(m), warp 64x32.
//   3-stage ring, K-step 32. Epilogue: exp(s/16) -> bf16 g_attnb +
//   deterministic per-block partial row sums -> g_psum.
// ---------------------------------------------------------------------------
#define SC_STAGE 32768
#define SC_SMEM  (3*SC_STAGE)

__global__ void __launch_bounds__(256) k_scores()
{
    extern __shared__ __align__(16) unsigned char dyn[];
    const uint32_t base = s2u(dyn);

    const int tid = threadIdx.x;
    const int w = tid >> 5, lane = tid & 31;
    const int gr = lane >> 2, tg = lane & 3;
    const int wrow = w & 1, wcol = w >> 1;
    const int m0 = blockIdx.x * 128;
    const int n0 = blockIdx.y * 128;
    const int b  = blockIdx.z;

    const __nv_bfloat16* srcs[4] = {
        g_q[0] + (size_t)b*Nn*Cc, g_q[1] + (size_t)b*Nn*Cc,
        g_k[0] + (size_t)b*Nn*Cc, g_k[1] + (size_t)b*Nn*Cc };
    const int rbase[4] = { n0, n0, m0, m0 };

    float acc[4][4][4];
    #pragma unroll
    for (int mf=0; mf<4; ++mf)
        #pragma unroll
        for (int nf=0; nf<4; ++nf)
            #pragma unroll
            for (int e=0; e<4; ++e) acc[mf][nf][e]=0.f;

    auto load_stage = [&](int s, int ck){
        const uint32_t st = base + s*SC_STAGE;
        #pragma unroll
        for (int t=0;t<4;++t){
            const uint32_t tb = st + t*8192;
            #pragma unroll
            for (int it=0; it<2; ++it){
                int idx = tid + 256*it;
                int r = idx>>2, c = idx&3;
                cpa16(sw64(tb, r, c), srcs[t] + (size_t)(rbase[t]+r)*Cc + ck + c*8);
            }
        }
        CP_COMMIT();
    };

    load_stage(0, 0);
    load_stage(1, 32);

    for (int kt = 0; kt < 8; ++kt) {
        const int s = kt % 3;
        if (kt < 7) { CP_WAIT(1); } else { CP_WAIT(0); }
        __syncthreads();
        if (kt + 2 < 8) load_stage((kt+2)%3, (kt+2)*32);

        const uint32_t st = base + s*SC_STAGE;
        #pragma unroll
        for (int p=0; p<2; ++p) {
            const uint32_t qt = st + p*8192;
            const uint32_t ktile = st + 16384 + p*8192;
            #pragma unroll
            for (int ks=0; ks<32; ks+=16) {
                uint32_t a[4][4];
                #pragma unroll
                for (int mf=0; mf<4; ++mf) {
                    int r = wrow*64 + mf*16 + (lane&15);
                    int c16 = (ks>>3) + (lane>>4);
                    ldsm4(a[mf], sw64(qt, r, c16));
                }
                #pragma unroll
                for (int nf2=0; nf2<2; ++nf2) {
                    int rr = wcol*32 + nf2*16 + (lane>>4)*8 + (lane&7);
                    int c16 = (ks>>3) + ((lane>>3)&1);
                    uint32_t bb[4];
                    ldsm4(bb, sw64(ktile, rr, c16));
                    #pragma unroll
                    for (int mf=0; mf<4; ++mf) {
                        mma16(acc[mf][nf2*2  ], a[mf], bb);
                        mma16(acc[mf][nf2*2+1], a[mf], bb+2);
                    }
                }
            }
        }
        __syncthreads();
    }

    // epilogue: exp + store + deterministic partial row sums
    float (*spsum)[128] = (float(*)[128])dyn;   // [wcol][row_local], 2KB
    const float sc = 1.0f/16.0f;
    #pragma unroll
    for (int mf=0; mf<4; ++mf) {
        const int row0 = n0 + wrow*64 + mf*16 + gr;
        const size_t r0b = (size_t)b*Nn*Nn + (size_t)row0*Nn;
        const size_t r1b = r0b + (size_t)8*Nn;
        float p0 = 0.f, p1 = 0.f;
        #pragma unroll
        for (int nfr=0; nfr<4; ++nfr) {
            const int col0 = m0 + wcol*32 + nfr*8 + 2*tg;
            float e0 = __expf(acc[mf][nfr][0]*sc);
            float e1 = __expf(acc[mf][nfr][1]*sc);
            float e2 = __expf(acc[mf][nfr][2]*sc);
            float e3 = __expf(acc[mf][nfr][3]*sc);
            *(uint32_t*)&g_attnb[r0b + col0] = packbf(e0, e1);
            *(uint32_t*)&g_attnb[r1b + col0] = packbf(e2, e3);
            p0 += e0 + e1;
            p1 += e2 + e3;
        }
        p0 += __shfl_xor_sync(0xFFFFFFFFu, p0, 1);
        p0 += __shfl_xor_sync(0xFFFFFFFFu, p0, 2);
        p1 += __shfl_xor_sync(0xFFFFFFFFu, p1, 1);
        p1 += __shfl_xor_sync(0xFFFFFFFFu, p1, 2);
        if (tg == 0) {
            spsum[wcol][wrow*64 + mf*16 + gr    ] = p0;
            spsum[wcol][wrow*64 + mf*16 + gr + 8] = p1;
        }
    }
    __syncthreads();
    if (tid < 128) {
        float s4 = spsum[0][tid] + spsum[1][tid] + spsum[2][tid] + spsum[3][tid];
        g_psum[((size_t)b*NMB + (m0>>7))*Nn + n0 + tid] = s4;
    }
}

// ---------------------------------------------------------------------------
// Kernel 3: row-sum reduce -> 1/sum
// ---------------------------------------------------------------------------
__global__ void __launch_bounds__(256) k_rowsum()
{
    const int i = blockIdx.x*256 + threadIdx.x;   // b*Nn + n
    const int b = i / Nn, n = i - b*Nn;
    float s = 0.f;
    #pragma unroll
    for (int mb=0; mb<NMB; ++mb)
        s += g_psum[((size_t)b*NMB + mb)*Nn + n];
    g_rinv[i] = 1.f / s;
}

// ---------------------------------------------------------------------------
// Kernel 4: AV. Block 128n x 64d, warps 4(n)x2(d). 3-stage ring, K-step 64.
// ---------------------------------------------------------------------------
#define AV_VOFF  16384
#define AV_STAGE (16384 + 18432)   // 34816
#define AV_SMEM  (3*AV_STAGE)      // 104448

__global__ void __launch_bounds__(256) k_av()
{
    extern __shared__ __align__(16) unsigned char dyn[];
    const uint32_t base = s2u(dyn);

    const int tid = threadIdx.x;
    const int w = tid >> 5, lane = tid & 31;
    const int gr = lane >> 2, tg = lane & 3;
    const int wm = w & 3, wn = w >> 2;
    const int n0 = blockIdx.x * 128;
    const int d0 = blockIdx.y * 64;
    const int b  = blockIdx.z;

    const __nv_bfloat16* Ab  = g_attnb + (size_t)b*Nn*Nn;
    const __nv_bfloat16* vp[2] = { g_v[0] + (size_t)b*Nn*Cc, g_v[1] + (size_t)b*Nn*Cc };

    float accr[2][4][4], acci[2][4][4];
    #pragma unroll
    for (int mf=0; mf<2; ++mf)
        #pragma unroll
        for (int nf=0; nf<4; ++nf)
            #pragma unroll
            for (int e=0; e<4; ++e){ accr[mf][nf][e]=0.f; acci[mf][nf][e]=0.f; }

    auto load_stage = [&](int s, int mk){
        const uint32_t st = base + s*AV_STAGE;
        #pragma unroll
        for (int it=0; it<4; ++it){
            int idx = tid + 256*it;
            int r = idx>>3, c = idx&7;
            cpa16(sw128(st, r, c), Ab + (size_t)(n0+r)*Nn + mk + c*8);
        }
        #pragma unroll
        for (int it=0; it<4; ++it){
            int idx = tid + 256*it;
            int p = idx>>9, r = (idx>>3)&63, c = idx&7;
            cpa16(st + AV_VOFF + p*9216 + r*144 + c*16,
                  vp[p] + (size_t)(mk+r)*Cc + d0 + c*8);
        }
        CP_COMMIT();
    };

    load_stage(0, 0);
    load_stage(1, 64);

    const int NKT = Nn/64;   // 36
    for (int kt = 0; kt < NKT; ++kt) {
        const int s = kt % 3;
        if (kt < NKT-1) { CP_WAIT(1); } else { CP_WAIT(0); }
        __syncthreads();
        if (kt + 2 < NKT) load_stage((kt+2)%3, (kt+2)*64);

        const uint32_t st = base + s*AV_STAGE;
        #pragma unroll
        for (int ks=0; ks<64; ks+=16) {
            uint32_t a[2][4];
            #pragma unroll
            for (int mf=0; mf<2; ++mf) {
                int r = wm*32 + mf*16 + (lane&15);
                int c16 = (ks>>3) + (lane>>4);
                ldsm4(a[mf], sw128(st, r, c16));
            }
            #pragma unroll
            for (int nf2=0; nf2<2; ++nf2) {
                int cb = wn*32 + nf2*16;
                uint32_t bvr[4], bvi[4];
                uint32_t vaddr = st + AV_VOFF + (uint32_t)(ks + (lane&15))*144 + (uint32_t)(cb + (lane>>4)*8)*2;
                ldsm4t(bvr, vaddr);
                ldsm4t(bvi, vaddr + 9216);
                #pragma unroll
                for (int h=0; h<2; ++h) {
                    int nfr = nf2*2 + h;
                    #pragma unroll
                    for (int mf=0; mf<2; ++mf) {
                        mma16(accr[mf][nfr], a[mf], bvr + 2*h);
                        mma16(acci[mf][nfr], a[mf], bvi + 2*h);
                    }
                }
            }
        }
        __syncthreads();
    }

    float rin[2][2];
    #pragma unroll
    for (int mf=0; mf<2; ++mf) {
        rin[mf][0] = g_rinv[(size_t)b*Nn + n0 + wm*32 + mf*16 + gr];
        rin[mf][1] = g_rinv[(size_t)b*Nn + n0 + wm*32 + mf*16 + gr + 8];
    }

    // transpose epilogue -> g_outT [d][n] bf16 (smem reuse)
    __nv_bfloat16 (*stage)[144] = (__nv_bfloat16(*)[144])dyn;
    const size_t basep = (size_t)b*Cc*Nn + (size_t)d0*Nn + n0;
    #pragma unroll
    for (int p=0; p<2; ++p) {
        __syncthreads();
        #pragma unroll
        for (int mf=0; mf<2; ++mf) {
            int rl = wm*32 + mf*16 + gr;
            #pragma unroll
            for (int nfr=0; nfr<4; ++nfr) {
                int cl = wn*32 + nfr*8 + 2*tg;
                float* acc = p ? acci[mf][nfr] : accr[mf][nfr];
                stage[cl  ][rl  ] = __float2bfloat16(acc[0]*rin[mf][0]);
                stage[cl+1][rl  ] = __float2bfloat16(acc[1]*rin[mf][0]);
                stage[cl  ][rl+8] = __float2bfloat16(acc[2]*rin[mf][1]);
                stage[cl+1][rl+8] = __float2bfloat16(acc[3]*rin[mf][1]);
            }
        }
        __syncthreads();
        #pragma unroll
        for (int it=0; it<4; ++it) {
            int idx = tid + 256*it;
            int dl = idx >> 4, c8 = idx & 15;
            *(uint4*)(g_outT[p] + basep + (size_t)dl*Nn + c8*8) = *(const uint4*)&stage[dl][c8*8];
        }
    }
}

// ---------------------------------------------------------------------------
// Kernel 5/6: BatchNorm (bf16 outT, vectorized)
// ---------------------------------------------------------------------------
__global__ void __launch_bounds__(256) k_bnstats(
    const float* __restrict__ xr, const float* __restrict__ xi,
    const float* __restrict__ gamma)
{
    const int c = blockIdx.x, p = blockIdx.y;
    const int tid = threadIdx.x;
    const float* x = p ? xi : xr;
    const __nv_bfloat16* o = g_outT[p];
    const float g = gamma[0];

    float s = 0.f, ss = 0.f;
    for (int b = 0; b < Bb; ++b) {
        const size_t bb = (size_t)b*Cc*Nn + (size_t)c*Nn;
        for (int n4 = tid; n4 < Nn/4; n4 += 256) {
            float4 xv = *(const float4*)(x + bb + n4*4);
            uint2 ou = *(const uint2*)(o + bb + n4*4);
            float2 o01 = __bfloat1622float2(*reinterpret_cast<const __nv_bfloat162*>(&ou.x));
            float2 o23 = __bfloat1622float2(*reinterpret_cast<const __nv_bfloat162*>(&ou.y));
            float z0 = xv.x + g*o01.x, z1 = xv.y + g*o01.y;
            float z2 = xv.z + g*o23.x, z3 = xv.w + g*o23.y;
            s  += z0+z1+z2+z3;
            ss += z0*z0+z1*z1+z2*z2+z3*z3;
        }
    }
    __shared__ float rs[256], rss[256];
    rs[tid] = s; rss[tid] = ss; __syncthreads();
    #pragma unroll
    for (int st = 128; st > 0; st >>= 1) {
        if (tid < st) { rs[tid] += rs[tid+st]; rss[tid] += rss[tid+st]; }
        __syncthreads();
    }
    if (tid == 0) {
        const float inv_cnt = 1.f / (float)Mtot;
        float mean = rs[0] * inv_cnt;
        float var  = rss[0] * inv_cnt - mean*mean;
        g_mean[p][c] = mean;
        g_rstd[p][c] = rsqrtf(var + EPSf);
    }
}

__global__ void __launch_bounds__(256) k_bnapply(
    const float* __restrict__ xr, const float* __restrict__ xi,
    const float* __restrict__ gamma,
    const float* __restrict__ bnwr, const float* __restrict__ bnbr,
    const float* __restrict__ bnwi, const float* __restrict__ bnbi,
    float* __restrict__ out)
{
    const int idx4 = blockIdx.x*256 + threadIdx.x;
    const size_t e = (size_t)idx4 * 4;
    const size_t half = (size_t)Bb*Cc*Nn;
    const int p = (e >= half) ? 1 : 0;
    const size_t rem = e - (size_t)p*half;
    const int c = (int)((rem / Nn) % Cc);

    const float* x = p ? xi : xr;
    const float g = gamma[0];
    const float wsc = (p ? bnwi[c] : bnwr[c]) * g_rstd[p][c];
    const float bia = (p ? bnbi[c] : bnbr[c]);
    const float mu = g_mean[p][c];

    float4 xv = *(const float4*)(x + rem);
    uint2 ou = *(const uint2*)(g_outT[p] + rem);
    float2 o01 = __bfloat1622float2(*reinterpret_cast<const __nv_bfloat162*>(&ou.x));
    float2 o23 = __bfloat1622float2(*reinterpret_cast<const __nv_bfloat162*>(&ou.y));

    float4 r;
    r.x = (xv.x + g*o01.x - mu) * wsc + bia;
    r.y = (xv.y + g*o01.y - mu) * wsc + bia;
    r.z = (xv.z + g*o23.x - mu) * wsc + bia;
    r.w = (xv.w + g*o23.y - mu) * wsc + bia;
    *(float4*)(out + e) = r;
}

// ---------------------------------------------------------------------------
// Launch
// ---------------------------------------------------------------------------
extern "C" void kernel_launch(void* const* d_in, const int* in_sizes, int n_in,
                              void* d_out, int out_size)
{
    const float* xr   = (const float*)d_in[0];
    const float* xi   = (const float*)d_in[1];
    const float* q_wr = (const float*)d_in[2];
    const float* q_wi = (const float*)d_in[3];
    const float* q_br = (const float*)d_in[4];
    const float* q_bi = (const float*)d_in[5];
    const float* k_wr = (const float*)d_in[6];
    const float* k_wi = (const float*)d_in[7];
    const float* k_br = (const float*)d_in[8];
    const float* k_bi = (const float*)d_in[9];
    const float* v_wr = (const float*)d_in[10];
    const float* v_wi = (const float*)d_in[11];
    const float* v_br = (const float*)d_in[12];
    const float* v_bi = (const float*)d_in[13];
    const float* gamma= (const float*)d_in[14];
    const float* bnwr = (const float*)d_in[15];
    const float* bnbr = (const float*)d_in[16];
    const float* bnwi = (const float*)d_in[17];
    const float* bnbi = (const float*)d_in[18];
    float* out = (float*)d_out;

    cudaFuncSetAttribute(k_proj,   cudaFuncAttributeMaxDynamicSharedMemorySize, PJ_SMEM);
    cudaFuncSetAttribute(k_scores, cudaFuncAttributeMaxDynamicSharedMemorySize, SC_SMEM);
    cudaFuncSetAttribute(k_av,     cudaFuncAttributeMaxDynamicSharedMemorySize, AV_SMEM);

    k_cvt<<<(2*(size_t)Bb*Cc*Nn/8)/256, 256>>>(xr, xi);
    k_cvtw<<<(6*Cc*Cc/8)/256, 256>>>(q_wr, q_wi, k_wr, k_wi, v_wr, v_wi);

    k_proj<<<dim3(Mtot/128, Cc/64, 3), 256, PJ_SMEM>>>(q_br, q_bi, k_br, k_bi, v_br, v_bi);

    k_scores<<<dim3(Nn/128, Nn/128, Bb), 256, SC_SMEM>>>();
    k_rowsum<<<Mtot/256, 256>>>();
    k_av<<<dim3(Nn/128, Cc/64, Bb), 256, AV_SMEM>>>();

    k_bnstats<<<dim3(Cc, 2), 256>>>(xr, xi, gamma);
    k_bnapply<<<(2*(size_t)Bb*Cc*Nn/4)/256, 256>>>(xr, xi, gamma, bnwr, bnbr, bnwi, bnbi, out);
}